// round 9
// baseline (speedup 1.0000x reference)
#include <cuda_runtime.h>
#include <math.h>
#include <stdint.h>

// GPT-2 small config
#define BSZ   2
#define TSEQ  1024
#define CDIM  768
#define FFDIM 3072
#define NHEAD 12
#define NLAYER 12
#define DHEAD 64
#define VOCAB 50257
#define NROW  (BSZ * TSEQ)   // 2048

// ---------------------------------------------------------------------------
// Scratch (device globals — no allocation allowed)
// ---------------------------------------------------------------------------
__device__ float g_x  [NROW * CDIM];
__device__ float g_h  [NROW * CDIM];
__device__ float g_qkv[NROW * 3 * CDIM];
__device__ float g_att[NROW * CDIM];
__device__ float g_ffn[NROW * FFDIM];

// ---------------------------------------------------------------------------
// Helpers
// ---------------------------------------------------------------------------
__device__ __forceinline__ float f2tf32(float x) {
    asm("cvt.rna.tf32.f32 %0, %0;" : "+f"(x));
    return x;
}

__device__ __forceinline__ void mma_tf32(float (&d)[4],
                                         const float (&a)[4],
                                         const float (&b)[2]) {
    asm volatile(
        "mma.sync.aligned.m16n8k8.row.col.f32.tf32.tf32.f32 "
        "{%0,%1,%2,%3}, {%4,%5,%6,%7}, {%8,%9}, {%0,%1,%2,%3};\n"
        : "+f"(d[0]), "+f"(d[1]), "+f"(d[2]), "+f"(d[3])
        : "r"(__float_as_uint(a[0])), "r"(__float_as_uint(a[1])),
          "r"(__float_as_uint(a[2])), "r"(__float_as_uint(a[3])),
          "r"(__float_as_uint(b[0])), "r"(__float_as_uint(b[1])));
}

__device__ __forceinline__ uint32_t smem_u32(const void* p) {
    uint32_t a;
    asm("{ .reg .u64 t; cvta.to.shared.u64 t, %1; cvt.u32.u64 %0, t; }"
        : "=r"(a) : "l"(p));
    return a;
}

__device__ __forceinline__ void cpa16(uint32_t dst, const float* src, int sz) {
    asm volatile("cp.async.cg.shared.global [%0], [%1], 16, %2;"
                 :: "r"(dst), "l"(src), "r"(sz));
}
__device__ __forceinline__ void cpa_commit() {
    asm volatile("cp.async.commit_group;" ::: "memory");
}
template <int N>
__device__ __forceinline__ void cpa_wait() {
    asm volatile("cp.async.wait_group %0;" :: "n"(N) : "memory");
}

// ---------------------------------------------------------------------------
// Embedding
// ---------------------------------------------------------------------------
__global__ void embed_kernel(const int* __restrict__ tokens,
                             const float* __restrict__ tok,
                             const float* __restrict__ pos,
                             float* __restrict__ x) {
    int n = blockIdx.x;
    int t = n % TSEQ;
    int tk = tokens[n];
    const float* tr = tok + (size_t)tk * CDIM;
    const float* pr = pos + (size_t)t * CDIM;
    float* xr = x + (size_t)n * CDIM;
    for (int c = threadIdx.x; c < CDIM; c += blockDim.x)
        xr[c] = tr[c] + pr[c];
}

// ---------------------------------------------------------------------------
// LayerNorm: warp per row, 8 rows per block. Row cached in registers
// between the stats pass and the write pass. Output tf32-rounded.
// ---------------------------------------------------------------------------
__global__ __launch_bounds__(256)
void ln_kernel(const float* __restrict__ x,
               const float* __restrict__ w,
               const float* __restrict__ b,
               float* __restrict__ out) {
    const int lane = threadIdx.x & 31;
    const int wrp  = threadIdx.x >> 5;
    const int n = blockIdx.x * 8 + wrp;
    const float* xr = x + (size_t)n * CDIM;

    float4 v[6];
    float s = 0.f, s2 = 0.f;
    #pragma unroll
    for (int i = 0; i < 6; i++) {
        v[i] = *(const float4*)(xr + i * 128 + lane * 4);
        s  += v[i].x + v[i].y + v[i].z + v[i].w;
        s2 += v[i].x * v[i].x + v[i].y * v[i].y
            + v[i].z * v[i].z + v[i].w * v[i].w;
    }
    #pragma unroll
    for (int o = 16; o; o >>= 1) {
        s  += __shfl_xor_sync(~0u, s,  o);
        s2 += __shfl_xor_sync(~0u, s2, o);
    }
    float m = s / CDIM;
    float var = s2 / CDIM - m * m;
    float r = rsqrtf(var + 1e-5f);

    float* orow = out + (size_t)n * CDIM;
    #pragma unroll
    for (int i = 0; i < 6; i++) {
        int c = i * 128 + lane * 4;
        float4 wv = *(const float4*)(w + c);
        float4 bv = *(const float4*)(b + c);
        float4 o;
        o.x = f2tf32((v[i].x - m) * r * wv.x + bv.x);
        o.y = f2tf32((v[i].y - m) * r * wv.y + bv.y);
        o.z = f2tf32((v[i].z - m) * r * wv.z + bv.z);
        o.w = f2tf32((v[i].w - m) * r * wv.w + bv.w);
        *(float4*)(orow + c) = o;
    }
}

// ---------------------------------------------------------------------------
// TF32 NT GEMM, cp.async 3-stage pipeline, BK=32 (unchanged from R6 — at
// ~93% of legacy tensor-pipe roofline).
// ---------------------------------------------------------------------------
#define GSTAGE_F 8192
#define GSMEM_BYTES (3 * GSTAGE_F * 4)

__device__ __forceinline__ int gsw(int r, int k) {
    return r * 32 + (((k >> 2) ^ (r & 7)) << 2) + (k & 3);
}

__global__ __launch_bounds__(256)
void gemm_tf32_kernel(const float* __restrict__ A, const float* __restrict__ W,
                      const float* __restrict__ bias, const float* __restrict__ res,
                      float* __restrict__ C, int N, int M, int K, int gelu) {
    extern __shared__ __align__(16) float smf[];

    const int tid  = threadIdx.x;
    const int lane = tid & 31;
    const int wid  = tid >> 5;
    const int g    = lane >> 2;
    const int tig  = lane & 3;
    const int warp_m = wid >> 2;
    const int warp_n = wid & 3;
    const int bm = blockIdx.y * 128;
    const int bn = blockIdx.x * 128;
    const uint32_t sbase = smem_u32(smf);

    const int lr = tid >> 3;
    const int lc = tid & 7;
    const uint32_t soff = (uint32_t)(lr * 32 + ((lc ^ (lr & 7)) << 2)) * 4u;

    float acc[4][4][4];
    #pragma unroll
    for (int mt = 0; mt < 4; mt++)
        #pragma unroll
        for (int nt = 0; nt < 4; nt++)
            #pragma unroll
            for (int r = 0; r < 4; r++) acc[mt][nt][r] = 0.f;

    const int KT = K / 32;

    auto issue = [&](int j) {
        const int k0 = j * 32;
        const uint32_t ab = sbase + (uint32_t)(j % 3) * GSTAGE_F * 4u;
        const uint32_t bb = ab + 4096u * 4u;
        #pragma unroll
        for (int i = 0; i < 4; i++) {
            int r = lr + i * 32;
            uint32_t rowoff = soff + (uint32_t)i * 32u * 32u * 4u;
            cpa16(ab + rowoff, A + (size_t)(bm + r) * K + k0 + lc * 4, 16);
            int m = bn + r;
            const float* ws = W + (size_t)(m < M ? m : 0) * K + k0 + lc * 4;
            cpa16(bb + rowoff, ws, (m < M) ? 16 : 0);
        }
    };

    issue(0); cpa_commit();
    if (KT > 1) issue(1);
    cpa_commit();

    for (int it = 0; it < KT; it++) {
        if (it + 2 < KT) issue(it + 2);
        cpa_commit();
        cpa_wait<2>();
        __syncthreads();

        const float* Asm = smf + (it % 3) * GSTAGE_F;
        const float* Bsm = Asm + 4096;

        #pragma unroll
        for (int ks = 0; ks < 4; ks++) {
            const int kb = ks * 8;
            float a[4][4], b[4][2];
            #pragma unroll
            for (int mt = 0; mt < 4; mt++) {
                int m0 = warp_m * 64 + mt * 16;
                a[mt][0] = Asm[gsw(m0 + g,     kb + tig)];
                a[mt][1] = Asm[gsw(m0 + g + 8, kb + tig)];
                a[mt][2] = Asm[gsw(m0 + g,     kb + tig + 4)];
                a[mt][3] = Asm[gsw(m0 + g + 8, kb + tig + 4)];
            }
            #pragma unroll
            for (int nt = 0; nt < 4; nt++) {
                int n0 = warp_n * 32 + nt * 8;
                b[nt][0] = f2tf32(Bsm[gsw(n0 + g, kb + tig)]);
                b[nt][1] = f2tf32(Bsm[gsw(n0 + g, kb + tig + 4)]);
            }
            #pragma unroll
            for (int mt = 0; mt < 4; mt++)
                #pragma unroll
                for (int nt = 0; nt < 4; nt++)
                    mma_tf32(acc[mt][nt], a[mt], b[nt]);
        }
        __syncthreads();
    }

    #pragma unroll
    for (int mt = 0; mt < 4; mt++) {
        #pragma unroll
        for (int nt = 0; nt < 4; nt++) {
            int col = bn + warp_n * 32 + nt * 8 + 2 * tig;
            #pragma unroll
            for (int rr = 0; rr < 2; rr++) {
                int row = bm + warp_m * 64 + mt * 16 + g + rr * 8;
                float v0 = acc[mt][nt][rr * 2 + 0];
                float v1 = acc[mt][nt][rr * 2 + 1];
                if (bias) { v0 += bias[col]; if (col + 1 < M) v1 += bias[col + 1]; }
                if (gelu) {
                    float u = v0;
                    v0 = f2tf32(0.5f * u * (1.f + tanhf(0.7978845608028654f *
                                                 (u + 0.044715f * u * u * u))));
                    u = v1;
                    v1 = f2tf32(0.5f * u * (1.f + tanhf(0.7978845608028654f *
                                                 (u + 0.044715f * u * u * u))));
                }
                size_t idx = (size_t)row * M + col;
                if (col + 1 < M) {
                    if (res) { v0 += res[idx]; v1 += res[idx + 1]; }
                    C[idx]     = v0;
                    C[idx + 1] = v1;
                } else if (col < M) {
                    if (res) v0 += res[idx];
                    C[idx] = v0;
                }
            }
        }
    }
}

// ---------------------------------------------------------------------------
// Tensor-core flash attention (tf32 mma).
// Block: 128 threads (4 warps), q-tile 64, k-tile 64. Warp owns a 16-row
// q band. P matrix staged in a per-warp smem buffer (stride 68:
// conflict-free A-frag reads, 2-way stores) — no cross-lane shuffles.
// __launch_bounds__(128,3): 3 blocks/SM.
// ---------------------------------------------------------------------------
#define ATQ 64
#define ATK 64
#define LOG2E 1.44269504088896f
#define PSTRIDE 68
#define ATTN_SMEM ((3 * 64 * 64 + 4 * 16 * PSTRIDE) * 4)   // 66560 B

__device__ __forceinline__ int tswz(int r, int c) {
    return r * 64 + ((((c >> 2) ^ ((r + (r >> 4)) & 15))) << 2) + (c & 3);
}

__global__ __launch_bounds__(128, 3)
void attn_kernel(const float* __restrict__ qkv, float* __restrict__ out) {
    extern __shared__ float sm[];
    float* Qs = sm;            // [64][64] swizzled
    float* Ks = sm + 4096;     // [64][64]
    float* Vt = sm + 8192;     // [d][j] transposed V

    const int qt = gridDim.x - 1 - blockIdx.x;   // heavy tiles first
    const int bh = blockIdx.y;
    const int b  = bh / NHEAD, h = bh % NHEAD;
    const int q0 = qt * ATQ;
    const int tid  = threadIdx.x;
    const int lane = tid & 31;
    const int wid  = tid >> 5;     // 0..3
    const int g    = lane >> 2;    // 0..7
    const int tig  = lane & 3;     // 0..3
    const int m0   = wid * 16;     // q-row band base
    float* Pw = sm + 12288 + wid * 16 * PSTRIDE;   // per-warp P [16][68]
    const size_t rstride = 3 * CDIM;
    const float qsc = 0.125f * LOG2E;   // scores in log2 domain

    // ---- stage Q (scaled + tf32) ----
    #pragma unroll
    for (int i = 0; i < 8; i++) {
        int f = i * 128 + tid;
        int r = f >> 4, c4 = (f & 15) * 4;
        float4 v = *(const float4*)(qkv + (size_t)(b * TSEQ + q0 + r) * rstride
                                    + h * DHEAD + c4);
        v.x = f2tf32(v.x * qsc); v.y = f2tf32(v.y * qsc);
        v.z = f2tf32(v.z * qsc); v.w = f2tf32(v.w * qsc);
        *(float4*)&Qs[tswz(r, c4)] = v;
    }

    float mrow[2] = {-1e30f, -1e30f};
    float lrow[2] = {0.f, 0.f};
    float O[8][4];
    #pragma unroll
    for (int nt = 0; nt < 8; nt++)
        #pragma unroll
        for (int r = 0; r < 4; r++) O[nt][r] = 0.f;

    for (int jt = 0; jt <= qt; jt++) {
        __syncthreads();
        // ---- stage K rows (tf32) ----
        #pragma unroll
        for (int i = 0; i < 8; i++) {
            int f = i * 128 + tid;
            int r = f >> 4, c4 = (f & 15) * 4;
            float4 v = *(const float4*)(qkv + (size_t)(b * TSEQ + jt * ATK + r) * rstride
                                        + CDIM + h * DHEAD + c4);
            v.x = f2tf32(v.x); v.y = f2tf32(v.y);
            v.z = f2tf32(v.z); v.w = f2tf32(v.w);
            *(float4*)&Ks[tswz(r, c4)] = v;
        }
        // ---- stage V transposed (tf32): Vt[d][j] = V[j][d] ----
        #pragma unroll
        for (int i = 0; i < 8; i++) {
            int f = i * 128 + tid;
            int j = f >> 4, d0 = (f & 15) * 4;
            float4 v = *(const float4*)(qkv + (size_t)(b * TSEQ + jt * ATK + j) * rstride
                                        + 2 * CDIM + h * DHEAD + d0);
            Vt[tswz(d0 + 0, j)] = f2tf32(v.x);
            Vt[tswz(d0 + 1, j)] = f2tf32(v.y);
            Vt[tswz(d0 + 2, j)] = f2tf32(v.z);
            Vt[tswz(d0 + 3, j)] = f2tf32(v.w);
        }
        __syncthreads();

        // ---- GEMM1: S = Q K^T  (warp tile 16 x 64) ----
        float s[8][4];
        #pragma unroll
        for (int nt = 0; nt < 8; nt++)
            #pragma unroll
            for (int r = 0; r < 4; r++) s[nt][r] = 0.f;

        #pragma unroll
        for (int ks = 0; ks < 8; ks++) {
            const int kb = ks * 8;
            float a[4];
            a[0] = Qs[tswz(m0 + g,     kb + tig)];
            a[1] = Qs[tswz(m0 + g + 8, kb + tig)];
            a[2] = Qs[tswz(m0 + g,     kb + tig + 4)];
            a[3] = Qs[tswz(m0 + g + 8, kb + tig + 4)];
            #pragma unroll
            for (int nt = 0; nt < 8; nt++) {
                float bb[2];
                bb[0] = Ks[tswz(nt * 8 + g, kb + tig)];
                bb[1] = Ks[tswz(nt * 8 + g, kb + tig + 4)];
                mma_tf32(s[nt], a, bb);
            }
        }

        // ---- causal mask + online softmax ----
        const int r0 = q0 + m0 + g, r1 = r0 + 8;
        const int jb = jt * ATK;
        float rx0 = -1e30f, rx1 = -1e30f;
        #pragma unroll
        for (int nt = 0; nt < 8; nt++) {
            int c0 = jb + nt * 8 + 2 * tig;
            if (c0     > r0) s[nt][0] = -1e30f;
            if (c0 + 1 > r0) s[nt][1] = -1e30f;
            if (c0     > r1) s[nt][2] = -1e30f;
            if (c0 + 1 > r1) s[nt][3] = -1e30f;
            rx0 = fmaxf(rx0, fmaxf(s[nt][0], s[nt][1]));
            rx1 = fmaxf(rx1, fmaxf(s[nt][2], s[nt][3]));
        }
        rx0 = fmaxf(rx0, __shfl_xor_sync(~0u, rx0, 1));
        rx0 = fmaxf(rx0, __shfl_xor_sync(~0u, rx0, 2));
        rx1 = fmaxf(rx1, __shfl_xor_sync(~0u, rx1, 1));
        rx1 = fmaxf(rx1, __shfl_xor_sync(~0u, rx1, 2));

        float mn0 = fmaxf(mrow[0], rx0);
        float mn1 = fmaxf(mrow[1], rx1);
        float fac0 = exp2f(mrow[0] - mn0);
        float fac1 = exp2f(mrow[1] - mn1);
        float ps0 = 0.f, ps1 = 0.f;
        #pragma unroll
        for (int nt = 0; nt < 8; nt++) {
            float p0 = f2tf32(exp2f(s[nt][0] - mn0));
            float p1 = f2tf32(exp2f(s[nt][1] - mn0));
            float p2 = f2tf32(exp2f(s[nt][2] - mn1));
            float p3 = f2tf32(exp2f(s[nt][3] - mn1));
            ps0 += p0 + p1; ps1 += p2 + p3;
            // store P fragments to per-warp smem (A-operand layout source)
            *(float2*)&Pw[g       * PSTRIDE + nt * 8 + 2 * tig] = make_float2(p0, p1);
            *(float2*)&Pw[(g + 8) * PSTRIDE + nt * 8 + 2 * tig] = make_float2(p2, p3);
        }
        ps0 += __shfl_xor_sync(~0u, ps0, 1);
        ps0 += __shfl_xor_sync(~0u, ps0, 2);
        ps1 += __shfl_xor_sync(~0u, ps1, 1);
        ps1 += __shfl_xor_sync(~0u, ps1, 2);
        lrow[0] = lrow[0] * fac0 + ps0;
        lrow[1] = lrow[1] * fac1 + ps1;
        mrow[0] = mn0; mrow[1] = mn1;

        #pragma unroll
        for (int nt = 0; nt < 8; nt++) {
            O[nt][0] *= fac0; O[nt][1] *= fac0;
            O[nt][2] *= fac1; O[nt][3] *= fac1;
        }
        __syncwarp();

        // ---- GEMM2: O += P V  (A-frags from per-warp smem P) ----
        #pragma unroll
        for (int ks = 0; ks < 8; ks++) {
            const int kb = ks * 8;
            float a[4];
            a[0] = Pw[g       * PSTRIDE + kb + tig];
            a[1] = Pw[(g + 8) * PSTRIDE + kb + tig];
            a[2] = Pw[g       * PSTRIDE + kb + tig + 4];
            a[3] = Pw[(g + 8) * PSTRIDE + kb + tig + 4];
            #pragma unroll
            for (int nt = 0; nt < 8; nt++) {
                float bb[2];
                bb[0] = Vt[tswz(nt * 8 + g, kb + tig)];
                bb[1] = Vt[tswz(nt * 8 + g, kb + tig + 4)];
                mma_tf32(O[nt], a, bb);
            }
        }
    }

    // ---- epilogue: normalize + store (tf32-rounded; feeds proj GEMM A) ----
    float inv0 = 1.f / lrow[0];
    float inv1 = 1.f / lrow[1];
    float* o0 = out + (size_t)(b * TSEQ + q0 + m0 + g) * CDIM + h * DHEAD;
    float* o1 = o0 + 8 * CDIM;
    #pragma unroll
    for (int nt = 0; nt < 8; nt++) {
        int c = nt * 8 + 2 * tig;
        float2 u0 = make_float2(f2tf32(O[nt][0] * inv0), f2tf32(O[nt][1] * inv0));
        float2 u1 = make_float2(f2tf32(O[nt][2] * inv1), f2tf32(O[nt][3] * inv1));
        *(float2*)(o0 + c) = u0;
        *(float2*)(o1 + c) = u1;
    }
}

// ---------------------------------------------------------------------------
// Launcher
// ---------------------------------------------------------------------------
extern "C" void kernel_launch(void* const* d_in, const int* in_sizes, int n_in,
                              void* d_out, int out_size) {
    const int*   tokens    = (const int*)  d_in[0];
    const float* tok_embed = (const float*)d_in[1];
    const float* pos_embed = (const float*)d_in[2];
    const float* ln1_w     = (const float*)d_in[3];
    const float* ln1_b     = (const float*)d_in[4];
    const float* qkv_w     = (const float*)d_in[5];
    const float* qkv_b     = (const float*)d_in[6];
    const float* proj_w    = (const float*)d_in[7];
    const float* proj_b    = (const float*)d_in[8];
    const float* ln2_w     = (const float*)d_in[9];
    const float* ln2_b     = (const float*)d_in[10];
    const float* fc_w      = (const float*)d_in[11];
    const float* fc_b      = (const float*)d_in[12];
    const float* fc2_w     = (const float*)d_in[13];
    const float* fc2_b     = (const float*)d_in[14];
    const float* lnf_w     = (const float*)d_in[15];
    const float* lnf_b     = (const float*)d_in[16];
    float* logits = (float*)d_out;

    float *x, *h, *qkv, *att, *ffn;
    cudaGetSymbolAddress((void**)&x,   g_x);
    cudaGetSymbolAddress((void**)&h,   g_h);
    cudaGetSymbolAddress((void**)&qkv, g_qkv);
    cudaGetSymbolAddress((void**)&att, g_att);
    cudaGetSymbolAddress((void**)&ffn, g_ffn);

    cudaFuncSetAttribute(attn_kernel,
                         cudaFuncAttributeMaxDynamicSharedMemorySize, ATTN_SMEM);
    cudaFuncSetAttribute(gemm_tf32_kernel,
                         cudaFuncAttributeMaxDynamicSharedMemorySize, GSMEM_BYTES);

    embed_kernel<<<NROW, 256>>>(tokens, tok_embed, pos_embed, x);

    const int NB = NROW / 128;   // 16 row-blocks
    for (int l = 0; l < NLAYER; l++) {
        const float* l1w = ln1_w  + (size_t)l * CDIM;
        const float* l1b = ln1_b  + (size_t)l * CDIM;
        const float* qw  = qkv_w  + (size_t)l * 3 * CDIM * CDIM;
        const float* qb  = qkv_b  + (size_t)l * 3 * CDIM;
        const float* pw  = proj_w + (size_t)l * CDIM * CDIM;
        const float* pb  = proj_b + (size_t)l * CDIM;
        const float* l2w = ln2_w  + (size_t)l * CDIM;
        const float* l2b = ln2_b  + (size_t)l * CDIM;
        const float* fw  = fc_w   + (size_t)l * FFDIM * CDIM;
        const float* fb  = fc_b   + (size_t)l * FFDIM;
        const float* f2w = fc2_w  + (size_t)l * CDIM * FFDIM;
        const float* f2b = fc2_b  + (size_t)l * CDIM;

        ln_kernel<<<NROW / 8, 256>>>(x, l1w, l1b, h);
        gemm_tf32_kernel<<<dim3(3 * CDIM / 128, NB), 256, GSMEM_BYTES>>>(
            h, qw, qb, nullptr, qkv, NROW, 3 * CDIM, CDIM, 0);
        attn_kernel<<<dim3(TSEQ / ATQ, BSZ * NHEAD), 128, ATTN_SMEM>>>(qkv, att);
        gemm_tf32_kernel<<<dim3(CDIM / 128, NB), 256, GSMEM_BYTES>>>(
            att, pw, pb, x, x, NROW, CDIM, CDIM, 0);
        ln_kernel<<<NROW / 8, 256>>>(x, l2w, l2b, h);
        gemm_tf32_kernel<<<dim3(FFDIM / 128, NB), 256, GSMEM_BYTES>>>(
            h, fw, fb, nullptr, ffn, NROW, FFDIM, CDIM, 1);
        gemm_tf32_kernel<<<dim3(CDIM / 128, NB), 256, GSMEM_BYTES>>>(
            ffn, f2w, f2b, x, x, NROW, CDIM, FFDIM, 0);
    }

    ln_kernel<<<NROW / 8, 256>>>(x, lnf_w, lnf_b, h);
    gemm_tf32_kernel<<<dim3((VOCAB + 127) / 128, NB), 256, GSMEM_BYTES>>>(
        h, tok_embed, nullptr, nullptr, logits, NROW, VOCAB, CDIM, 0);
}

// round 11
// speedup vs baseline: 1.1231x; 1.1231x over previous
#include <cuda_runtime.h>
#include <math.h>
#include <stdint.h>

// GPT-2 small config
#define BSZ   2
#define TSEQ  1024
#define CDIM  768
#define FFDIM 3072
#define NHEAD 12
#define NLAYER 12
#define DHEAD 64
#define VOCAB 50257
#define NROW  (BSZ * TSEQ)   // 2048

// ---------------------------------------------------------------------------
// Scratch (device globals — no allocation allowed)
// ---------------------------------------------------------------------------
__device__ float g_x  [NROW * CDIM];
__device__ float g_h  [NROW * CDIM];
__device__ float g_qkv[NROW * 3 * CDIM];
__device__ float g_att[NROW * CDIM];
__device__ float g_ffn[NROW * FFDIM];

// ---------------------------------------------------------------------------
// Helpers
// ---------------------------------------------------------------------------
__device__ __forceinline__ float f2tf32(float x) {
    asm("cvt.rna.tf32.f32 %0, %0;" : "+f"(x));
    return x;
}

__device__ __forceinline__ void mma_tf32(float (&d)[4],
                                         const float (&a)[4],
                                         const float (&b)[2]) {
    asm volatile(
        "mma.sync.aligned.m16n8k8.row.col.f32.tf32.tf32.f32 "
        "{%0,%1,%2,%3}, {%4,%5,%6,%7}, {%8,%9}, {%0,%1,%2,%3};\n"
        : "+f"(d[0]), "+f"(d[1]), "+f"(d[2]), "+f"(d[3])
        : "r"(__float_as_uint(a[0])), "r"(__float_as_uint(a[1])),
          "r"(__float_as_uint(a[2])), "r"(__float_as_uint(a[3])),
          "r"(__float_as_uint(b[0])), "r"(__float_as_uint(b[1])));
}

__device__ __forceinline__ uint32_t smem_u32(const void* p) {
    uint32_t a;
    asm("{ .reg .u64 t; cvta.to.shared.u64 t, %1; cvt.u32.u64 %0, t; }"
        : "=r"(a) : "l"(p));
    return a;
}

__device__ __forceinline__ void cpa16(uint32_t dst, const float* src, int sz) {
    asm volatile("cp.async.cg.shared.global [%0], [%1], 16, %2;"
                 :: "r"(dst), "l"(src), "r"(sz));
}
__device__ __forceinline__ void cpa_commit() {
    asm volatile("cp.async.commit_group;" ::: "memory");
}
template <int N>
__device__ __forceinline__ void cpa_wait() {
    asm volatile("cp.async.wait_group %0;" :: "n"(N) : "memory");
}

// ---------------------------------------------------------------------------
// Embedding
// ---------------------------------------------------------------------------
__global__ void embed_kernel(const int* __restrict__ tokens,
                             const float* __restrict__ tok,
                             const float* __restrict__ pos,
                             float* __restrict__ x) {
    int n = blockIdx.x;
    int t = n % TSEQ;
    int tk = tokens[n];
    const float* tr = tok + (size_t)tk * CDIM;
    const float* pr = pos + (size_t)t * CDIM;
    float* xr = x + (size_t)n * CDIM;
    for (int c = threadIdx.x; c < CDIM; c += blockDim.x)
        xr[c] = tr[c] + pr[c];
}

// ---------------------------------------------------------------------------
// LayerNorm: warp per row, 8 rows/block, row cached in regs. tf32-rounded out.
// ---------------------------------------------------------------------------
__global__ __launch_bounds__(256)
void ln_kernel(const float* __restrict__ x,
               const float* __restrict__ w,
               const float* __restrict__ b,
               float* __restrict__ out) {
    const int lane = threadIdx.x & 31;
    const int wrp  = threadIdx.x >> 5;
    const int n = blockIdx.x * 8 + wrp;
    const float* xr = x + (size_t)n * CDIM;

    float4 v[6];
    float s = 0.f, s2 = 0.f;
    #pragma unroll
    for (int i = 0; i < 6; i++) {
        v[i] = *(const float4*)(xr + i * 128 + lane * 4);
        s  += v[i].x + v[i].y + v[i].z + v[i].w;
        s2 += v[i].x * v[i].x + v[i].y * v[i].y
            + v[i].z * v[i].z + v[i].w * v[i].w;
    }
    #pragma unroll
    for (int o = 16; o; o >>= 1) {
        s  += __shfl_xor_sync(~0u, s,  o);
        s2 += __shfl_xor_sync(~0u, s2, o);
    }
    float m = s / CDIM;
    float var = s2 / CDIM - m * m;
    float r = rsqrtf(var + 1e-5f);

    float* orow = out + (size_t)n * CDIM;
    #pragma unroll
    for (int i = 0; i < 6; i++) {
        int c = i * 128 + lane * 4;
        float4 wv = *(const float4*)(w + c);
        float4 bv = *(const float4*)(b + c);
        float4 o;
        o.x = f2tf32((v[i].x - m) * r * wv.x + bv.x);
        o.y = f2tf32((v[i].y - m) * r * wv.y + bv.y);
        o.z = f2tf32((v[i].z - m) * r * wv.z + bv.z);
        o.w = f2tf32((v[i].w - m) * r * wv.w + bv.w);
        *(float4*)(orow + c) = o;
    }
}

// ---------------------------------------------------------------------------
// TF32 NT GEMM, cp.async 3-stage pipeline, BK=32, optional split-K.
// C[n,m] = sum_k A[n,k]*W[m,k] (+bias, +GELU, +residual).
// Split-K (gridDim.z = S > 1): each split covers K/S; partials are
// atomicAdd-ed into C (which must already hold the residual); bias added
// by split 0 only. gelu/res unsupported in split mode (not needed).
// ---------------------------------------------------------------------------
#define GSTAGE_F 8192
#define GSMEM_BYTES (3 * GSTAGE_F * 4)

__device__ __forceinline__ int gsw(int r, int k) {
    return r * 32 + (((k >> 2) ^ (r & 7)) << 2) + (k & 3);
}

__global__ __launch_bounds__(256)
void gemm_tf32_kernel(const float* __restrict__ A, const float* __restrict__ W,
                      const float* __restrict__ bias, const float* __restrict__ res,
                      float* __restrict__ C, int N, int M, int K, int gelu) {
    extern __shared__ __align__(16) float smf[];

    const int tid  = threadIdx.x;
    const int lane = tid & 31;
    const int wid  = tid >> 5;
    const int g    = lane >> 2;
    const int tig  = lane & 3;
    const int warp_m = wid >> 2;
    const int warp_n = wid & 3;
    const int bm = blockIdx.y * 128;
    const int bn = blockIdx.x * 128;
    const int S     = gridDim.z;
    const int split = blockIdx.z;
    const int Ks     = K / S;           // per-split K extent
    const int k0base = split * Ks;
    const uint32_t sbase = smem_u32(smf);

    const int lr = tid >> 3;
    const int lc = tid & 7;
    const uint32_t soff = (uint32_t)(lr * 32 + ((lc ^ (lr & 7)) << 2)) * 4u;

    float acc[4][4][4];
    #pragma unroll
    for (int mt = 0; mt < 4; mt++)
        #pragma unroll
        for (int nt = 0; nt < 4; nt++)
            #pragma unroll
            for (int r = 0; r < 4; r++) acc[mt][nt][r] = 0.f;

    const int KT = Ks / 32;

    auto issue = [&](int j) {
        const int k0 = k0base + j * 32;
        const uint32_t ab = sbase + (uint32_t)(j % 3) * GSTAGE_F * 4u;
        const uint32_t bb = ab + 4096u * 4u;
        #pragma unroll
        for (int i = 0; i < 4; i++) {
            int r = lr + i * 32;
            uint32_t rowoff = soff + (uint32_t)i * 32u * 32u * 4u;
            cpa16(ab + rowoff, A + (size_t)(bm + r) * K + k0 + lc * 4, 16);
            int m = bn + r;
            const float* ws = W + (size_t)(m < M ? m : 0) * K + k0 + lc * 4;
            cpa16(bb + rowoff, ws, (m < M) ? 16 : 0);
        }
    };

    issue(0); cpa_commit();
    if (KT > 1) issue(1);
    cpa_commit();

    for (int it = 0; it < KT; it++) {
        if (it + 2 < KT) issue(it + 2);
        cpa_commit();
        cpa_wait<2>();
        __syncthreads();

        const float* Asm = smf + (it % 3) * GSTAGE_F;
        const float* Bsm = Asm + 4096;

        #pragma unroll
        for (int ks = 0; ks < 4; ks++) {
            const int kb = ks * 8;
            float a[4][4], b[4][2];
            #pragma unroll
            for (int mt = 0; mt < 4; mt++) {
                int m0 = warp_m * 64 + mt * 16;
                a[mt][0] = Asm[gsw(m0 + g,     kb + tig)];
                a[mt][1] = Asm[gsw(m0 + g + 8, kb + tig)];
                a[mt][2] = Asm[gsw(m0 + g,     kb + tig + 4)];
                a[mt][3] = Asm[gsw(m0 + g + 8, kb + tig + 4)];
            }
            #pragma unroll
            for (int nt = 0; nt < 4; nt++) {
                int n0 = warp_n * 32 + nt * 8;
                b[nt][0] = f2tf32(Bsm[gsw(n0 + g, kb + tig)]);
                b[nt][1] = f2tf32(Bsm[gsw(n0 + g, kb + tig + 4)]);
            }
            #pragma unroll
            for (int mt = 0; mt < 4; mt++)
                #pragma unroll
                for (int nt = 0; nt < 4; nt++)
                    mma_tf32(acc[mt][nt], a[mt], b[nt]);
        }
        __syncthreads();
    }

    #pragma unroll
    for (int mt = 0; mt < 4; mt++) {
        #pragma unroll
        for (int nt = 0; nt < 4; nt++) {
            int col = bn + warp_n * 32 + nt * 8 + 2 * tig;
            #pragma unroll
            for (int rr = 0; rr < 2; rr++) {
                int row = bm + warp_m * 64 + mt * 16 + g + rr * 8;
                float v0 = acc[mt][nt][rr * 2 + 0];
                float v1 = acc[mt][nt][rr * 2 + 1];
                size_t idx = (size_t)row * M + col;
                if (S > 1) {
                    // split-K: accumulate into C (residual already there)
                    if (split == 0 && bias) { v0 += bias[col]; v1 += bias[col + 1]; }
                    atomicAdd(&C[idx],     v0);
                    atomicAdd(&C[idx + 1], v1);
                    continue;
                }
                if (bias) { v0 += bias[col]; if (col + 1 < M) v1 += bias[col + 1]; }
                if (gelu) {
                    float u = v0;
                    v0 = f2tf32(0.5f * u * (1.f + tanhf(0.7978845608028654f *
                                                 (u + 0.044715f * u * u * u))));
                    u = v1;
                    v1 = f2tf32(0.5f * u * (1.f + tanhf(0.7978845608028654f *
                                                 (u + 0.044715f * u * u * u))));
                }
                if (col + 1 < M) {
                    if (res) { v0 += res[idx]; v1 += res[idx + 1]; }
                    C[idx]     = v0;
                    C[idx + 1] = v1;
                } else if (col < M) {
                    if (res) v0 += res[idx];
                    C[idx] = v0;
                }
            }
        }
    }
}

// ---------------------------------------------------------------------------
// Tensor-core flash attention (tf32 mma) — R7-validated shuffle version.
// ---------------------------------------------------------------------------
#define ATQ 64
#define ATK 64
#define LOG2E 1.44269504088896f
#define ATTN_SMEM (3 * 64 * 64 * 4)

__device__ __forceinline__ int tswz(int r, int c) {
    return r * 64 + ((((c >> 2) ^ ((r + (r >> 4)) & 15))) << 2) + (c & 3);
}

__global__ __launch_bounds__(128)
void attn_kernel(const float* __restrict__ qkv, float* __restrict__ out) {
    extern __shared__ float sm[];
    float* Qs = sm;
    float* Ks = sm + 4096;
    float* Vt = sm + 8192;

    const int qt = gridDim.x - 1 - blockIdx.x;
    const int bh = blockIdx.y;
    const int b  = bh / NHEAD, h = bh % NHEAD;
    const int q0 = qt * ATQ;
    const int tid  = threadIdx.x;
    const int lane = tid & 31;
    const int wid  = tid >> 5;
    const int g    = lane >> 2;
    const int tig  = lane & 3;
    const int m0   = wid * 16;
    const size_t rstride = 3 * CDIM;
    const float qsc = 0.125f * LOG2E;

    #pragma unroll
    for (int i = 0; i < 8; i++) {
        int f = i * 128 + tid;
        int r = f >> 4, c4 = (f & 15) * 4;
        float4 v = *(const float4*)(qkv + (size_t)(b * TSEQ + q0 + r) * rstride
                                    + h * DHEAD + c4);
        v.x = f2tf32(v.x * qsc); v.y = f2tf32(v.y * qsc);
        v.z = f2tf32(v.z * qsc); v.w = f2tf32(v.w * qsc);
        *(float4*)&Qs[tswz(r, c4)] = v;
    }

    float mrow[2] = {-1e30f, -1e30f};
    float lrow[2] = {0.f, 0.f};
    float O[8][4];
    #pragma unroll
    for (int nt = 0; nt < 8; nt++)
        #pragma unroll
        for (int r = 0; r < 4; r++) O[nt][r] = 0.f;

    const int src1 = (g << 2) | (tig >> 1);
    const int src2 = src1 + 2;
    const bool odd = (tig & 1);

    for (int jt = 0; jt <= qt; jt++) {
        __syncthreads();
        #pragma unroll
        for (int i = 0; i < 8; i++) {
            int f = i * 128 + tid;
            int r = f >> 4, c4 = (f & 15) * 4;
            float4 v = *(const float4*)(qkv + (size_t)(b * TSEQ + jt * ATK + r) * rstride
                                        + CDIM + h * DHEAD + c4);
            v.x = f2tf32(v.x); v.y = f2tf32(v.y);
            v.z = f2tf32(v.z); v.w = f2tf32(v.w);
            *(float4*)&Ks[tswz(r, c4)] = v;
        }
        #pragma unroll
        for (int i = 0; i < 8; i++) {
            int f = i * 128 + tid;
            int j = f >> 4, d0 = (f & 15) * 4;
            float4 v = *(const float4*)(qkv + (size_t)(b * TSEQ + jt * ATK + j) * rstride
                                        + 2 * CDIM + h * DHEAD + d0);
            Vt[tswz(d0 + 0, j)] = f2tf32(v.x);
            Vt[tswz(d0 + 1, j)] = f2tf32(v.y);
            Vt[tswz(d0 + 2, j)] = f2tf32(v.z);
            Vt[tswz(d0 + 3, j)] = f2tf32(v.w);
        }
        __syncthreads();

        float s[8][4];
        #pragma unroll
        for (int nt = 0; nt < 8; nt++)
            #pragma unroll
            for (int r = 0; r < 4; r++) s[nt][r] = 0.f;

        #pragma unroll
        for (int ks = 0; ks < 8; ks++) {
            const int kb = ks * 8;
            float a[4];
            a[0] = Qs[tswz(m0 + g,     kb + tig)];
            a[1] = Qs[tswz(m0 + g + 8, kb + tig)];
            a[2] = Qs[tswz(m0 + g,     kb + tig + 4)];
            a[3] = Qs[tswz(m0 + g + 8, kb + tig + 4)];
            #pragma unroll
            for (int nt = 0; nt < 8; nt++) {
                float bb[2];
                bb[0] = Ks[tswz(nt * 8 + g, kb + tig)];
                bb[1] = Ks[tswz(nt * 8 + g, kb + tig + 4)];
                mma_tf32(s[nt], a, bb);
            }
        }

        const int r0 = q0 + m0 + g, r1 = r0 + 8;
        const int jb = jt * ATK;
        float rx0 = -1e30f, rx1 = -1e30f;
        #pragma unroll
        for (int nt = 0; nt < 8; nt++) {
            int c0 = jb + nt * 8 + 2 * tig;
            if (c0     > r0) s[nt][0] = -1e30f;
            if (c0 + 1 > r0) s[nt][1] = -1e30f;
            if (c0     > r1) s[nt][2] = -1e30f;
            if (c0 + 1 > r1) s[nt][3] = -1e30f;
            rx0 = fmaxf(rx0, fmaxf(s[nt][0], s[nt][1]));
            rx1 = fmaxf(rx1, fmaxf(s[nt][2], s[nt][3]));
        }
        rx0 = fmaxf(rx0, __shfl_xor_sync(~0u, rx0, 1));
        rx0 = fmaxf(rx0, __shfl_xor_sync(~0u, rx0, 2));
        rx1 = fmaxf(rx1, __shfl_xor_sync(~0u, rx1, 1));
        rx1 = fmaxf(rx1, __shfl_xor_sync(~0u, rx1, 2));

        float mn0 = fmaxf(mrow[0], rx0);
        float mn1 = fmaxf(mrow[1], rx1);
        float fac0 = exp2f(mrow[0] - mn0);
        float fac1 = exp2f(mrow[1] - mn1);
        float ps0 = 0.f, ps1 = 0.f;
        #pragma unroll
        for (int nt = 0; nt < 8; nt++) {
            float p0 = f2tf32(exp2f(s[nt][0] - mn0));
            float p1 = f2tf32(exp2f(s[nt][1] - mn0));
            float p2 = f2tf32(exp2f(s[nt][2] - mn1));
            float p3 = f2tf32(exp2f(s[nt][3] - mn1));
            s[nt][0] = p0; s[nt][1] = p1; s[nt][2] = p2; s[nt][3] = p3;
            ps0 += p0 + p1; ps1 += p2 + p3;
        }
        ps0 += __shfl_xor_sync(~0u, ps0, 1);
        ps0 += __shfl_xor_sync(~0u, ps0, 2);
        ps1 += __shfl_xor_sync(~0u, ps1, 1);
        ps1 += __shfl_xor_sync(~0u, ps1, 2);
        lrow[0] = lrow[0] * fac0 + ps0;
        lrow[1] = lrow[1] * fac1 + ps1;
        mrow[0] = mn0; mrow[1] = mn1;

        #pragma unroll
        for (int nt = 0; nt < 8; nt++) {
            O[nt][0] *= fac0; O[nt][1] *= fac0;
            O[nt][2] *= fac1; O[nt][3] *= fac1;
        }

        #pragma unroll
        for (int ks = 0; ks < 8; ks++) {
            float v0 = __shfl_sync(~0u, s[ks][0], src1);
            float v1 = __shfl_sync(~0u, s[ks][1], src1);
            float v2 = __shfl_sync(~0u, s[ks][2], src1);
            float v3 = __shfl_sync(~0u, s[ks][3], src1);
            float w0 = __shfl_sync(~0u, s[ks][0], src2);
            float w1 = __shfl_sync(~0u, s[ks][1], src2);
            float w2 = __shfl_sync(~0u, s[ks][2], src2);
            float w3 = __shfl_sync(~0u, s[ks][3], src2);
            float a[4];
            a[0] = odd ? v1 : v0;
            a[1] = odd ? v3 : v2;
            a[2] = odd ? w1 : w0;
            a[3] = odd ? w3 : w2;
            const int kb = ks * 8;
            #pragma unroll
            for (int nt = 0; nt < 8; nt++) {
                float bb[2];
                bb[0] = Vt[tswz(nt * 8 + g, kb + tig)];
                bb[1] = Vt[tswz(nt * 8 + g, kb + tig + 4)];
                mma_tf32(O[nt], a, bb);
            }
        }
    }

    float inv0 = 1.f / lrow[0];
    float inv1 = 1.f / lrow[1];
    float* o0 = out + (size_t)(b * TSEQ + q0 + m0 + g) * CDIM + h * DHEAD;
    float* o1 = o0 + 8 * CDIM;
    #pragma unroll
    for (int nt = 0; nt < 8; nt++) {
        int c = nt * 8 + 2 * tig;
        float2 u0 = make_float2(f2tf32(O[nt][0] * inv0), f2tf32(O[nt][1] * inv0));
        float2 u1 = make_float2(f2tf32(O[nt][2] * inv1), f2tf32(O[nt][3] * inv1));
        *(float2*)(o0 + c) = u0;
        *(float2*)(o1 + c) = u1;
    }
}

// ---------------------------------------------------------------------------
// Launcher
// ---------------------------------------------------------------------------
extern "C" void kernel_launch(void* const* d_in, const int* in_sizes, int n_in,
                              void* d_out, int out_size) {
    const int*   tokens    = (const int*)  d_in[0];
    const float* tok_embed = (const float*)d_in[1];
    const float* pos_embed = (const float*)d_in[2];
    const float* ln1_w     = (const float*)d_in[3];
    const float* ln1_b     = (const float*)d_in[4];
    const float* qkv_w     = (const float*)d_in[5];
    const float* qkv_b     = (const float*)d_in[6];
    const float* proj_w    = (const float*)d_in[7];
    const float* proj_b    = (const float*)d_in[8];
    const float* ln2_w     = (const float*)d_in[9];
    const float* ln2_b     = (const float*)d_in[10];
    const float* fc_w      = (const float*)d_in[11];
    const float* fc_b      = (const float*)d_in[12];
    const float* fc2_w     = (const float*)d_in[13];
    const float* fc2_b     = (const float*)d_in[14];
    const float* lnf_w     = (const float*)d_in[15];
    const float* lnf_b     = (const float*)d_in[16];
    float* logits = (float*)d_out;

    float *x, *h, *qkv, *att, *ffn;
    cudaGetSymbolAddress((void**)&x,   g_x);
    cudaGetSymbolAddress((void**)&h,   g_h);
    cudaGetSymbolAddress((void**)&qkv, g_qkv);
    cudaGetSymbolAddress((void**)&att, g_att);
    cudaGetSymbolAddress((void**)&ffn, g_ffn);

    cudaFuncSetAttribute(attn_kernel,
                         cudaFuncAttributeMaxDynamicSharedMemorySize, ATTN_SMEM);
    cudaFuncSetAttribute(gemm_tf32_kernel,
                         cudaFuncAttributeMaxDynamicSharedMemorySize, GSMEM_BYTES);

    embed_kernel<<<NROW, 256>>>(tokens, tok_embed, pos_embed, x);

    const int NB = NROW / 128;   // 16 row-blocks
    for (int l = 0; l < NLAYER; l++) {
        const float* l1w = ln1_w  + (size_t)l * CDIM;
        const float* l1b = ln1_b  + (size_t)l * CDIM;
        const float* qw  = qkv_w  + (size_t)l * 3 * CDIM * CDIM;
        const float* qb  = qkv_b  + (size_t)l * 3 * CDIM;
        const float* pw  = proj_w + (size_t)l * CDIM * CDIM;
        const float* pb  = proj_b + (size_t)l * CDIM;
        const float* l2w = ln2_w  + (size_t)l * CDIM;
        const float* l2b = ln2_b  + (size_t)l * CDIM;
        const float* fw  = fc_w   + (size_t)l * FFDIM * CDIM;
        const float* fb  = fc_b   + (size_t)l * FFDIM;
        const float* f2w = fc2_w  + (size_t)l * CDIM * FFDIM;
        const float* f2b = fc2_b  + (size_t)l * CDIM;

        ln_kernel<<<NROW / 8, 256>>>(x, l1w, l1b, h);
        gemm_tf32_kernel<<<dim3(3 * CDIM / 128, NB), 256, GSMEM_BYTES>>>(
            h, qw, qb, nullptr, qkv, NROW, 3 * CDIM, CDIM, 0);
        attn_kernel<<<dim3(TSEQ / ATQ, BSZ * NHEAD), 128, ATTN_SMEM>>>(qkv, att);
        // proj: split-K=3, x += att @ pw^T + pb (atomic, in place)
        gemm_tf32_kernel<<<dim3(CDIM / 128, NB, 3), 256, GSMEM_BYTES>>>(
            att, pw, pb, nullptr, x, NROW, CDIM, CDIM, 0);
        ln_kernel<<<NROW / 8, 256>>>(x, l2w, l2b, h);
        gemm_tf32_kernel<<<dim3(FFDIM / 128, NB), 256, GSMEM_BYTES>>>(
            h, fw, fb, nullptr, ffn, NROW, FFDIM, CDIM, 1);
        // fc2: split-K=3, x += ffn @ f2w^T + f2b (atomic, in place)
        gemm_tf32_kernel<<<dim3(CDIM / 128, NB, 3), 256, GSMEM_BYTES>>>(
            ffn, f2w, f2b, nullptr, x, NROW, CDIM, FFDIM, 0);
    }

    ln_kernel<<<NROW / 8, 256>>>(x, lnf_w, lnf_b, h);
    gemm_tf32_kernel<<<dim3((VOCAB + 127) / 128, NB), 256, GSMEM_BYTES>>>(
        h, tok_embed, nullptr, nullptr, logits, NROW, VOCAB, CDIM, 0);
}

// round 12
// speedup vs baseline: 1.1790x; 1.0498x over previous
#include <cuda_runtime.h>
#include <math.h>
#include <stdint.h>

// GPT-2 small config
#define BSZ   2
#define TSEQ  1024
#define CDIM  768
#define FFDIM 3072
#define NHEAD 12
#define NLAYER 12
#define DHEAD 64
#define VOCAB 50257
#define NROW  (BSZ * TSEQ)   // 2048

// ---------------------------------------------------------------------------
// Scratch (device globals — no allocation allowed)
// ---------------------------------------------------------------------------
__device__ float g_x  [NROW * CDIM];
__device__ float g_h  [NROW * CDIM];
__device__ float g_qkv[NROW * 3 * CDIM];
__device__ float g_att[NROW * CDIM];
__device__ float g_ffn[NROW * FFDIM];

// ---------------------------------------------------------------------------
// Helpers
// ---------------------------------------------------------------------------
__device__ __forceinline__ float f2tf32(float x) {
    asm("cvt.rna.tf32.f32 %0, %0;" : "+f"(x));
    return x;
}

__device__ __forceinline__ void mma_tf32(float (&d)[4],
                                         const float (&a)[4],
                                         const float (&b)[2]) {
    asm volatile(
        "mma.sync.aligned.m16n8k8.row.col.f32.tf32.tf32.f32 "
        "{%0,%1,%2,%3}, {%4,%5,%6,%7}, {%8,%9}, {%0,%1,%2,%3};\n"
        : "+f"(d[0]), "+f"(d[1]), "+f"(d[2]), "+f"(d[3])
        : "r"(__float_as_uint(a[0])), "r"(__float_as_uint(a[1])),
          "r"(__float_as_uint(a[2])), "r"(__float_as_uint(a[3])),
          "r"(__float_as_uint(b[0])), "r"(__float_as_uint(b[1])));
}

__device__ __forceinline__ uint32_t smem_u32(const void* p) {
    uint32_t a;
    asm("{ .reg .u64 t; cvta.to.shared.u64 t, %1; cvt.u32.u64 %0, t; }"
        : "=r"(a) : "l"(p));
    return a;
}

__device__ __forceinline__ void cpa16(uint32_t dst, const float* src, int sz) {
    asm volatile("cp.async.cg.shared.global [%0], [%1], 16, %2;"
                 :: "r"(dst), "l"(src), "r"(sz));
}
__device__ __forceinline__ void cpa_commit() {
    asm volatile("cp.async.commit_group;" ::: "memory");
}
template <int N>
__device__ __forceinline__ void cpa_wait() {
    asm volatile("cp.async.wait_group %0;" :: "n"(N) : "memory");
}

// ---------------------------------------------------------------------------
// Embedding
// ---------------------------------------------------------------------------
__global__ void embed_kernel(const int* __restrict__ tokens,
                             const float* __restrict__ tok,
                             const float* __restrict__ pos,
                             float* __restrict__ x) {
    int n = blockIdx.x;
    int t = n % TSEQ;
    int tk = tokens[n];
    const float* tr = tok + (size_t)tk * CDIM;
    const float* pr = pos + (size_t)t * CDIM;
    float* xr = x + (size_t)n * CDIM;
    for (int c = threadIdx.x; c < CDIM; c += blockDim.x)
        xr[c] = tr[c] + pr[c];
}

// ---------------------------------------------------------------------------
// LayerNorm: warp per row, 8 rows/block, row cached in regs. tf32-rounded out.
// ---------------------------------------------------------------------------
__global__ __launch_bounds__(256)
void ln_kernel(const float* __restrict__ x,
               const float* __restrict__ w,
               const float* __restrict__ b,
               float* __restrict__ out) {
    const int lane = threadIdx.x & 31;
    const int wrp  = threadIdx.x >> 5;
    const int n = blockIdx.x * 8 + wrp;
    const float* xr = x + (size_t)n * CDIM;

    float4 v[6];
    float s = 0.f, s2 = 0.f;
    #pragma unroll
    for (int i = 0; i < 6; i++) {
        v[i] = *(const float4*)(xr + i * 128 + lane * 4);
        s  += v[i].x + v[i].y + v[i].z + v[i].w;
        s2 += v[i].x * v[i].x + v[i].y * v[i].y
            + v[i].z * v[i].z + v[i].w * v[i].w;
    }
    #pragma unroll
    for (int o = 16; o; o >>= 1) {
        s  += __shfl_xor_sync(~0u, s,  o);
        s2 += __shfl_xor_sync(~0u, s2, o);
    }
    float m = s / CDIM;
    float var = s2 / CDIM - m * m;
    float r = rsqrtf(var + 1e-5f);

    float* orow = out + (size_t)n * CDIM;
    #pragma unroll
    for (int i = 0; i < 6; i++) {
        int c = i * 128 + lane * 4;
        float4 wv = *(const float4*)(w + c);
        float4 bv = *(const float4*)(b + c);
        float4 o;
        o.x = f2tf32((v[i].x - m) * r * wv.x + bv.x);
        o.y = f2tf32((v[i].y - m) * r * wv.y + bv.y);
        o.z = f2tf32((v[i].z - m) * r * wv.z + bv.z);
        o.w = f2tf32((v[i].w - m) * r * wv.w + bv.w);
        *(float4*)(orow + c) = o;
    }
}

// ---------------------------------------------------------------------------
// TF32 NT GEMM, cp.async 3-stage pipeline, BK=32, optional split-K.
// (unchanged from R10 — at ~95% of the legacy tensor-pipe roofline)
// ---------------------------------------------------------------------------
#define GSTAGE_F 8192
#define GSMEM_BYTES (3 * GSTAGE_F * 4)

__device__ __forceinline__ int gsw(int r, int k) {
    return r * 32 + (((k >> 2) ^ (r & 7)) << 2) + (k & 3);
}

__global__ __launch_bounds__(256)
void gemm_tf32_kernel(const float* __restrict__ A, const float* __restrict__ W,
                      const float* __restrict__ bias, const float* __restrict__ res,
                      float* __restrict__ C, int N, int M, int K, int gelu) {
    extern __shared__ __align__(16) float smf[];

    const int tid  = threadIdx.x;
    const int lane = tid & 31;
    const int wid  = tid >> 5;
    const int g    = lane >> 2;
    const int tig  = lane & 3;
    const int warp_m = wid >> 2;
    const int warp_n = wid & 3;
    const int bm = blockIdx.y * 128;
    const int bn = blockIdx.x * 128;
    const int S     = gridDim.z;
    const int split = blockIdx.z;
    const int Ks     = K / S;
    const int k0base = split * Ks;
    const uint32_t sbase = smem_u32(smf);

    const int lr = tid >> 3;
    const int lc = tid & 7;
    const uint32_t soff = (uint32_t)(lr * 32 + ((lc ^ (lr & 7)) << 2)) * 4u;

    float acc[4][4][4];
    #pragma unroll
    for (int mt = 0; mt < 4; mt++)
        #pragma unroll
        for (int nt = 0; nt < 4; nt++)
            #pragma unroll
            for (int r = 0; r < 4; r++) acc[mt][nt][r] = 0.f;

    const int KT = Ks / 32;

    auto issue = [&](int j) {
        const int k0 = k0base + j * 32;
        const uint32_t ab = sbase + (uint32_t)(j % 3) * GSTAGE_F * 4u;
        const uint32_t bb = ab + 4096u * 4u;
        #pragma unroll
        for (int i = 0; i < 4; i++) {
            int r = lr + i * 32;
            uint32_t rowoff = soff + (uint32_t)i * 32u * 32u * 4u;
            cpa16(ab + rowoff, A + (size_t)(bm + r) * K + k0 + lc * 4, 16);
            int m = bn + r;
            const float* ws = W + (size_t)(m < M ? m : 0) * K + k0 + lc * 4;
            cpa16(bb + rowoff, ws, (m < M) ? 16 : 0);
        }
    };

    issue(0); cpa_commit();
    if (KT > 1) issue(1);
    cpa_commit();

    for (int it = 0; it < KT; it++) {
        if (it + 2 < KT) issue(it + 2);
        cpa_commit();
        cpa_wait<2>();
        __syncthreads();

        const float* Asm = smf + (it % 3) * GSTAGE_F;
        const float* Bsm = Asm + 4096;

        #pragma unroll
        for (int ks = 0; ks < 4; ks++) {
            const int kb = ks * 8;
            float a[4][4], b[4][2];
            #pragma unroll
            for (int mt = 0; mt < 4; mt++) {
                int m0 = warp_m * 64 + mt * 16;
                a[mt][0] = Asm[gsw(m0 + g,     kb + tig)];
                a[mt][1] = Asm[gsw(m0 + g + 8, kb + tig)];
                a[mt][2] = Asm[gsw(m0 + g,     kb + tig + 4)];
                a[mt][3] = Asm[gsw(m0 + g + 8, kb + tig + 4)];
            }
            #pragma unroll
            for (int nt = 0; nt < 4; nt++) {
                int n0 = warp_n * 32 + nt * 8;
                b[nt][0] = f2tf32(Bsm[gsw(n0 + g, kb + tig)]);
                b[nt][1] = f2tf32(Bsm[gsw(n0 + g, kb + tig + 4)]);
            }
            #pragma unroll
            for (int mt = 0; mt < 4; mt++)
                #pragma unroll
                for (int nt = 0; nt < 4; nt++)
                    mma_tf32(acc[mt][nt], a[mt], b[nt]);
        }
        __syncthreads();
    }

    #pragma unroll
    for (int mt = 0; mt < 4; mt++) {
        #pragma unroll
        for (int nt = 0; nt < 4; nt++) {
            int col = bn + warp_n * 32 + nt * 8 + 2 * tig;
            #pragma unroll
            for (int rr = 0; rr < 2; rr++) {
                int row = bm + warp_m * 64 + mt * 16 + g + rr * 8;
                float v0 = acc[mt][nt][rr * 2 + 0];
                float v1 = acc[mt][nt][rr * 2 + 1];
                size_t idx = (size_t)row * M + col;
                if (S > 1) {
                    if (split == 0 && bias) { v0 += bias[col]; v1 += bias[col + 1]; }
                    atomicAdd(&C[idx],     v0);
                    atomicAdd(&C[idx + 1], v1);
                    continue;
                }
                if (bias) { v0 += bias[col]; if (col + 1 < M) v1 += bias[col + 1]; }
                if (gelu) {
                    float u = v0;
                    v0 = f2tf32(0.5f * u * (1.f + tanhf(0.7978845608028654f *
                                                 (u + 0.044715f * u * u * u))));
                    u = v1;
                    v1 = f2tf32(0.5f * u * (1.f + tanhf(0.7978845608028654f *
                                                 (u + 0.044715f * u * u * u))));
                }
                if (col + 1 < M) {
                    if (res) { v0 += res[idx]; v1 += res[idx + 1]; }
                    C[idx]     = v0;
                    C[idx + 1] = v1;
                } else if (col < M) {
                    if (res) v0 += res[idx];
                    C[idx] = v0;
                }
            }
        }
    }
}

// ---------------------------------------------------------------------------
// Tensor-core flash attention (tf32 mma), cp.async double-buffered K/V.
// Block: 128 threads (4 warps), q-tile 64, k-tile 64; warp owns a 16-row
// q band. K layout: tswz (row-major, validated). V layout: row-major with
// row-keyed chunk swizzle vswz — transposed fragment reads conflict-free.
// K/V fed to mma as raw fp32 (HW tf32 truncation).
// Smem: Q 16KB + 2 x (K 16KB + V 16KB) = 80KB.
// ---------------------------------------------------------------------------
#define ATQ 64
#define ATK 64
#define LOG2E 1.44269504088896f
#define ATTN_SMEM (5 * 4096 * 4)   // 81920 B

__device__ __forceinline__ int tswz(int r, int c) {
    return r * 64 + ((((c >> 2) ^ ((r + (r >> 4)) & 15))) << 2) + (c & 3);
}
// V swizzle: chunk ^= (r&3)<<1 — conflict-free for transposed reads
// V[kb+tig(+4)][nt*8+g] and for 16B row stores.
__device__ __forceinline__ int vswz(int r, int c) {
    return r * 64 + ((((c >> 2) ^ ((r & 3) << 1))) << 2) + (c & 3);
}

__global__ __launch_bounds__(128)
void attn_kernel(const float* __restrict__ qkv, float* __restrict__ out) {
    extern __shared__ float sm[];
    float* Qs = sm;                       // [64][64] tswz

    const int qt = gridDim.x - 1 - blockIdx.x;   // heavy tiles first
    const int bh = blockIdx.y;
    const int b  = bh / NHEAD, h = bh % NHEAD;
    const int q0 = qt * ATQ;
    const int tid  = threadIdx.x;
    const int lane = tid & 31;
    const int wid  = tid >> 5;
    const int g    = lane >> 2;
    const int tig  = lane & 3;
    const int m0   = wid * 16;
    const size_t rstride = 3 * CDIM;
    const float qsc = 0.125f * LOG2E;
    const uint32_t sbase = smem_u32(sm);

    // ---- stage Q (scaled + tf32 RNA) ----
    #pragma unroll
    for (int i = 0; i < 8; i++) {
        int f = i * 128 + tid;
        int r = f >> 4, c4 = (f & 15) * 4;
        float4 v = *(const float4*)(qkv + (size_t)(b * TSEQ + q0 + r) * rstride
                                    + h * DHEAD + c4);
        v.x = f2tf32(v.x * qsc); v.y = f2tf32(v.y * qsc);
        v.z = f2tf32(v.z * qsc); v.w = f2tf32(v.w * qsc);
        *(float4*)&Qs[tswz(r, c4)] = v;
    }

    // cp.async K/V tile loader: buffer (jt&1)
    const int lr0 = tid >> 4;      // 0..7
    const int lch = tid & 15;      // 16B chunk in row
    auto issueKV = [&](int jt2) {
        if (jt2 > qt) return;
        const int jr = jt2 * ATK;
        const uint32_t kbase = sbase + (4096u + (uint32_t)(jt2 & 1) * 8192u) * 4u;
        const uint32_t vbase = kbase + 4096u * 4u;
        #pragma unroll
        for (int i = 0; i < 8; i++) {
            int r = lr0 + i * 8;
            const float* src = qkv + (size_t)(b * TSEQ + jr + r) * rstride
                               + h * DHEAD + lch * 4;
            uint32_t koff = (uint32_t)(r * 64 + ((lch ^ ((r + (r >> 4)) & 15)) << 2)) * 4u;
            uint32_t voff = (uint32_t)(r * 64 + ((lch ^ ((r & 3) << 1)) << 2)) * 4u;
            cpa16(kbase + koff, src + CDIM,     16);
            cpa16(vbase + voff, src + 2 * CDIM, 16);
        }
    };

    issueKV(0); cpa_commit();

    float mrow[2] = {-1e30f, -1e30f};
    float lrow[2] = {0.f, 0.f};
    float O[8][4];
    #pragma unroll
    for (int nt = 0; nt < 8; nt++)
        #pragma unroll
        for (int r = 0; r < 4; r++) O[nt][r] = 0.f;

    const int src1 = (g << 2) | (tig >> 1);
    const int src2 = src1 + 2;
    const bool odd = (tig & 1);

    for (int jt = 0; jt <= qt; jt++) {
        issueKV(jt + 1); cpa_commit();
        cpa_wait<1>();
        __syncthreads();

        const float* Ks = sm + 4096 + (jt & 1) * 8192;
        const float* Vs = Ks + 4096;

        // ---- GEMM1: S = Q K^T  (warp tile 16 x 64) ----
        float s[8][4];
        #pragma unroll
        for (int nt = 0; nt < 8; nt++)
            #pragma unroll
            for (int r = 0; r < 4; r++) s[nt][r] = 0.f;

        #pragma unroll
        for (int ks = 0; ks < 8; ks++) {
            const int kb = ks * 8;
            float a[4];
            a[0] = Qs[tswz(m0 + g,     kb + tig)];
            a[1] = Qs[tswz(m0 + g + 8, kb + tig)];
            a[2] = Qs[tswz(m0 + g,     kb + tig + 4)];
            a[3] = Qs[tswz(m0 + g + 8, kb + tig + 4)];
            #pragma unroll
            for (int nt = 0; nt < 8; nt++) {
                float bb[2];
                bb[0] = Ks[tswz(nt * 8 + g, kb + tig)];
                bb[1] = Ks[tswz(nt * 8 + g, kb + tig + 4)];
                mma_tf32(s[nt], a, bb);
            }
        }

        // ---- causal mask + online softmax ----
        const int r0 = q0 + m0 + g, r1 = r0 + 8;
        const int jb = jt * ATK;
        float rx0 = -1e30f, rx1 = -1e30f;
        #pragma unroll
        for (int nt = 0; nt < 8; nt++) {
            int c0 = jb + nt * 8 + 2 * tig;
            if (c0     > r0) s[nt][0] = -1e30f;
            if (c0 + 1 > r0) s[nt][1] = -1e30f;
            if (c0     > r1) s[nt][2] = -1e30f;
            if (c0 + 1 > r1) s[nt][3] = -1e30f;
            rx0 = fmaxf(rx0, fmaxf(s[nt][0], s[nt][1]));
            rx1 = fmaxf(rx1, fmaxf(s[nt][2], s[nt][3]));
        }
        rx0 = fmaxf(rx0, __shfl_xor_sync(~0u, rx0, 1));
        rx0 = fmaxf(rx0, __shfl_xor_sync(~0u, rx0, 2));
        rx1 = fmaxf(rx1, __shfl_xor_sync(~0u, rx1, 1));
        rx1 = fmaxf(rx1, __shfl_xor_sync(~0u, rx1, 2));

        float mn0 = fmaxf(mrow[0], rx0);
        float mn1 = fmaxf(mrow[1], rx1);
        float fac0 = exp2f(mrow[0] - mn0);
        float fac1 = exp2f(mrow[1] - mn1);
        float ps0 = 0.f, ps1 = 0.f;
        #pragma unroll
        for (int nt = 0; nt < 8; nt++) {
            float p0 = f2tf32(exp2f(s[nt][0] - mn0));
            float p1 = f2tf32(exp2f(s[nt][1] - mn0));
            float p2 = f2tf32(exp2f(s[nt][2] - mn1));
            float p3 = f2tf32(exp2f(s[nt][3] - mn1));
            s[nt][0] = p0; s[nt][1] = p1; s[nt][2] = p2; s[nt][3] = p3;
            ps0 += p0 + p1; ps1 += p2 + p3;
        }
        ps0 += __shfl_xor_sync(~0u, ps0, 1);
        ps0 += __shfl_xor_sync(~0u, ps0, 2);
        ps1 += __shfl_xor_sync(~0u, ps1, 1);
        ps1 += __shfl_xor_sync(~0u, ps1, 2);
        lrow[0] = lrow[0] * fac0 + ps0;
        lrow[1] = lrow[1] * fac1 + ps1;
        mrow[0] = mn0; mrow[1] = mn1;

        #pragma unroll
        for (int nt = 0; nt < 8; nt++) {
            O[nt][0] *= fac0; O[nt][1] *= fac0;
            O[nt][2] *= fac1; O[nt][3] *= fac1;
        }

        // ---- GEMM2: O += P V  (A-frags via quad shuffles; B from vswz V) ----
        #pragma unroll
        for (int ks = 0; ks < 8; ks++) {
            float v0 = __shfl_sync(~0u, s[ks][0], src1);
            float v1 = __shfl_sync(~0u, s[ks][1], src1);
            float v2 = __shfl_sync(~0u, s[ks][2], src1);
            float v3 = __shfl_sync(~0u, s[ks][3], src1);
            float w0 = __shfl_sync(~0u, s[ks][0], src2);
            float w1 = __shfl_sync(~0u, s[ks][1], src2);
            float w2 = __shfl_sync(~0u, s[ks][2], src2);
            float w3 = __shfl_sync(~0u, s[ks][3], src2);
            float a[4];
            a[0] = odd ? v1 : v0;
            a[1] = odd ? v3 : v2;
            a[2] = odd ? w1 : w0;
            a[3] = odd ? w3 : w2;
            const int kb = ks * 8;
            #pragma unroll
            for (int nt = 0; nt < 8; nt++) {
                float bb[2];
                bb[0] = Vs[vswz(kb + tig,     nt * 8 + g)];
                bb[1] = Vs[vswz(kb + tig + 4, nt * 8 + g)];
                mma_tf32(O[nt], a, bb);
            }
        }
        __syncthreads();   // compute done before buffer (jt&1) is overwritten
    }

    float inv0 = 1.f / lrow[0];
    float inv1 = 1.f / lrow[1];
    float* o0 = out + (size_t)(b * TSEQ + q0 + m0 + g) * CDIM + h * DHEAD;
    float* o1 = o0 + 8 * CDIM;
    #pragma unroll
    for (int nt = 0; nt < 8; nt++) {
        int c = nt * 8 + 2 * tig;
        float2 u0 = make_float2(f2tf32(O[nt][0] * inv0), f2tf32(O[nt][1] * inv0));
        float2 u1 = make_float2(f2tf32(O[nt][2] * inv1), f2tf32(O[nt][3] * inv1));
        *(float2*)(o0 + c) = u0;
        *(float2*)(o1 + c) = u1;
    }
}

// ---------------------------------------------------------------------------
// Launcher
// ---------------------------------------------------------------------------
extern "C" void kernel_launch(void* const* d_in, const int* in_sizes, int n_in,
                              void* d_out, int out_size) {
    const int*   tokens    = (const int*)  d_in[0];
    const float* tok_embed = (const float*)d_in[1];
    const float* pos_embed = (const float*)d_in[2];
    const float* ln1_w     = (const float*)d_in[3];
    const float* ln1_b     = (const float*)d_in[4];
    const float* qkv_w     = (const float*)d_in[5];
    const float* qkv_b     = (const float*)d_in[6];
    const float* proj_w    = (const float*)d_in[7];
    const float* proj_b    = (const float*)d_in[8];
    const float* ln2_w     = (const float*)d_in[9];
    const float* ln2_b     = (const float*)d_in[10];
    const float* fc_w      = (const float*)d_in[11];
    const float* fc_b      = (const float*)d_in[12];
    const float* fc2_w     = (const float*)d_in[13];
    const float* fc2_b     = (const float*)d_in[14];
    const float* lnf_w     = (const float*)d_in[15];
    const float* lnf_b     = (const float*)d_in[16];
    float* logits = (float*)d_out;

    float *x, *h, *qkv, *att, *ffn;
    cudaGetSymbolAddress((void**)&x,   g_x);
    cudaGetSymbolAddress((void**)&h,   g_h);
    cudaGetSymbolAddress((void**)&qkv, g_qkv);
    cudaGetSymbolAddress((void**)&att, g_att);
    cudaGetSymbolAddress((void**)&ffn, g_ffn);

    cudaFuncSetAttribute(attn_kernel,
                         cudaFuncAttributeMaxDynamicSharedMemorySize, ATTN_SMEM);
    cudaFuncSetAttribute(gemm_tf32_kernel,
                         cudaFuncAttributeMaxDynamicSharedMemorySize, GSMEM_BYTES);

    embed_kernel<<<NROW, 256>>>(tokens, tok_embed, pos_embed, x);

    const int NB = NROW / 128;   // 16 row-blocks
    for (int l = 0; l < NLAYER; l++) {
        const float* l1w = ln1_w  + (size_t)l * CDIM;
        const float* l1b = ln1_b  + (size_t)l * CDIM;
        const float* qw  = qkv_w  + (size_t)l * 3 * CDIM * CDIM;
        const float* qb  = qkv_b  + (size_t)l * 3 * CDIM;
        const float* pw  = proj_w + (size_t)l * CDIM * CDIM;
        const float* pb  = proj_b + (size_t)l * CDIM;
        const float* l2w = ln2_w  + (size_t)l * CDIM;
        const float* l2b = ln2_b  + (size_t)l * CDIM;
        const float* fw  = fc_w   + (size_t)l * FFDIM * CDIM;
        const float* fb  = fc_b   + (size_t)l * FFDIM;
        const float* f2w = fc2_w  + (size_t)l * CDIM * FFDIM;
        const float* f2b = fc2_b  + (size_t)l * CDIM;

        ln_kernel<<<NROW / 8, 256>>>(x, l1w, l1b, h);
        gemm_tf32_kernel<<<dim3(3 * CDIM / 128, NB), 256, GSMEM_BYTES>>>(
            h, qw, qb, nullptr, qkv, NROW, 3 * CDIM, CDIM, 0);
        attn_kernel<<<dim3(TSEQ / ATQ, BSZ * NHEAD), 128, ATTN_SMEM>>>(qkv, att);
        // proj: split-K=3, x += att @ pw^T + pb (atomic, in place)
        gemm_tf32_kernel<<<dim3(CDIM / 128, NB, 3), 256, GSMEM_BYTES>>>(
            att, pw, pb, nullptr, x, NROW, CDIM, CDIM, 0);
        ln_kernel<<<NROW / 8, 256>>>(x, l2w, l2b, h);
        gemm_tf32_kernel<<<dim3(FFDIM / 128, NB), 256, GSMEM_BYTES>>>(
            h, fw, fb, nullptr, ffn, NROW, FFDIM, CDIM, 1);
        // fc2: split-K=3, x += ffn @ f2w^T + f2b (atomic, in place)
        gemm_tf32_kernel<<<dim3(CDIM / 128, NB, 3), 256, GSMEM_BYTES>>>(
            ffn, f2w, f2b, nullptr, x, NROW, CDIM, FFDIM, 0);
    }

    ln_kernel<<<NROW / 8, 256>>>(x, lnf_w, lnf_b, h);
    gemm_tf32_kernel<<<dim3((VOCAB + 127) / 128, NB), 256, GSMEM_BYTES>>>(
        h, tok_embed, nullptr, nullptr, logits, NROW, VOCAB, CDIM, 0);
}

// round 13
// speedup vs baseline: 1.1963x; 1.0147x over previous
#include <cuda_runtime.h>
#include <math.h>
#include <stdint.h>

// GPT-2 small config
#define BSZ   2
#define TSEQ  1024
#define CDIM  768
#define FFDIM 3072
#define NHEAD 12
#define NLAYER 12
#define DHEAD 64
#define VOCAB 50257
#define NROW  (BSZ * TSEQ)   // 2048

// ---------------------------------------------------------------------------
// Scratch (device globals — no allocation allowed)
// ---------------------------------------------------------------------------
__device__ float g_x  [NROW * CDIM];
__device__ float g_h  [NROW * CDIM];
__device__ float g_qkv[NROW * 3 * CDIM];
__device__ float g_att[NROW * CDIM];
__device__ float g_ffn[NROW * FFDIM];

// ---------------------------------------------------------------------------
// Helpers
// ---------------------------------------------------------------------------
__device__ __forceinline__ float f2tf32(float x) {
    asm("cvt.rna.tf32.f32 %0, %0;" : "+f"(x));
    return x;
}

__device__ __forceinline__ void mma_tf32(float (&d)[4],
                                         const float (&a)[4],
                                         const float (&b)[2]) {
    asm volatile(
        "mma.sync.aligned.m16n8k8.row.col.f32.tf32.tf32.f32 "
        "{%0,%1,%2,%3}, {%4,%5,%6,%7}, {%8,%9}, {%0,%1,%2,%3};\n"
        : "+f"(d[0]), "+f"(d[1]), "+f"(d[2]), "+f"(d[3])
        : "r"(__float_as_uint(a[0])), "r"(__float_as_uint(a[1])),
          "r"(__float_as_uint(a[2])), "r"(__float_as_uint(a[3])),
          "r"(__float_as_uint(b[0])), "r"(__float_as_uint(b[1])));
}

__device__ __forceinline__ uint32_t smem_u32(const void* p) {
    uint32_t a;
    asm("{ .reg .u64 t; cvta.to.shared.u64 t, %1; cvt.u32.u64 %0, t; }"
        : "=r"(a) : "l"(p));
    return a;
}

__device__ __forceinline__ void cpa16(uint32_t dst, const float* src, int sz) {
    asm volatile("cp.async.cg.shared.global [%0], [%1], 16, %2;"
                 :: "r"(dst), "l"(src), "r"(sz));
}
__device__ __forceinline__ void cpa_commit() {
    asm volatile("cp.async.commit_group;" ::: "memory");
}
template <int N>
__device__ __forceinline__ void cpa_wait() {
    asm volatile("cp.async.wait_group %0;" :: "n"(N) : "memory");
}

// ---------------------------------------------------------------------------
// Embedding
// ---------------------------------------------------------------------------
__global__ void embed_kernel(const int* __restrict__ tokens,
                             const float* __restrict__ tok,
                             const float* __restrict__ pos,
                             float* __restrict__ x) {
    int n = blockIdx.x;
    int t = n % TSEQ;
    int tk = tokens[n];
    const float* tr = tok + (size_t)tk * CDIM;
    const float* pr = pos + (size_t)t * CDIM;
    float* xr = x + (size_t)n * CDIM;
    for (int c = threadIdx.x; c < CDIM; c += blockDim.x)
        xr[c] = tr[c] + pr[c];
}

// ---------------------------------------------------------------------------
// LayerNorm: warp per row, 8 rows/block, row cached in regs. tf32-rounded out.
// ---------------------------------------------------------------------------
__global__ __launch_bounds__(256)
void ln_kernel(const float* __restrict__ x,
               const float* __restrict__ w,
               const float* __restrict__ b,
               float* __restrict__ out) {
    const int lane = threadIdx.x & 31;
    const int wrp  = threadIdx.x >> 5;
    const int n = blockIdx.x * 8 + wrp;
    const float* xr = x + (size_t)n * CDIM;

    float4 v[6];
    float s = 0.f, s2 = 0.f;
    #pragma unroll
    for (int i = 0; i < 6; i++) {
        v[i] = *(const float4*)(xr + i * 128 + lane * 4);
        s  += v[i].x + v[i].y + v[i].z + v[i].w;
        s2 += v[i].x * v[i].x + v[i].y * v[i].y
            + v[i].z * v[i].z + v[i].w * v[i].w;
    }
    #pragma unroll
    for (int o = 16; o; o >>= 1) {
        s  += __shfl_xor_sync(~0u, s,  o);
        s2 += __shfl_xor_sync(~0u, s2, o);
    }
    float m = s / CDIM;
    float var = s2 / CDIM - m * m;
    float r = rsqrtf(var + 1e-5f);

    float* orow = out + (size_t)n * CDIM;
    #pragma unroll
    for (int i = 0; i < 6; i++) {
        int c = i * 128 + lane * 4;
        float4 wv = *(const float4*)(w + c);
        float4 bv = *(const float4*)(b + c);
        float4 o;
        o.x = f2tf32((v[i].x - m) * r * wv.x + bv.x);
        o.y = f2tf32((v[i].y - m) * r * wv.y + bv.y);
        o.z = f2tf32((v[i].z - m) * r * wv.z + bv.z);
        o.w = f2tf32((v[i].w - m) * r * wv.w + bv.w);
        *(float4*)(orow + c) = o;
    }
}

// ---------------------------------------------------------------------------
// TF32 NT GEMM, cp.async 3-stage pipeline, BK=32, optional split-K.
// rnd=1: tf32-round (RNA) outputs in the plain-store path (used for the QKV
// GEMM so attention's cp.async-staged K/V are already exact tf32 values).
// ---------------------------------------------------------------------------
#define GSTAGE_F 8192
#define GSMEM_BYTES (3 * GSTAGE_F * 4)

__device__ __forceinline__ int gsw(int r, int k) {
    return r * 32 + (((k >> 2) ^ (r & 7)) << 2) + (k & 3);
}

__global__ __launch_bounds__(256)
void gemm_tf32_kernel(const float* __restrict__ A, const float* __restrict__ W,
                      const float* __restrict__ bias, const float* __restrict__ res,
                      float* __restrict__ C, int N, int M, int K, int gelu,
                      int rnd) {
    extern __shared__ __align__(16) float smf[];

    const int tid  = threadIdx.x;
    const int lane = tid & 31;
    const int wid  = tid >> 5;
    const int g    = lane >> 2;
    const int tig  = lane & 3;
    const int warp_m = wid >> 2;
    const int warp_n = wid & 3;
    const int bm = blockIdx.y * 128;
    const int bn = blockIdx.x * 128;
    const int S     = gridDim.z;
    const int split = blockIdx.z;
    const int Ks     = K / S;
    const int k0base = split * Ks;
    const uint32_t sbase = smem_u32(smf);

    const int lr = tid >> 3;
    const int lc = tid & 7;
    const uint32_t soff = (uint32_t)(lr * 32 + ((lc ^ (lr & 7)) << 2)) * 4u;

    float acc[4][4][4];
    #pragma unroll
    for (int mt = 0; mt < 4; mt++)
        #pragma unroll
        for (int nt = 0; nt < 4; nt++)
            #pragma unroll
            for (int r = 0; r < 4; r++) acc[mt][nt][r] = 0.f;

    const int KT = Ks / 32;

    auto issue = [&](int j) {
        const int k0 = k0base + j * 32;
        const uint32_t ab = sbase + (uint32_t)(j % 3) * GSTAGE_F * 4u;
        const uint32_t bb = ab + 4096u * 4u;
        #pragma unroll
        for (int i = 0; i < 4; i++) {
            int r = lr + i * 32;
            uint32_t rowoff = soff + (uint32_t)i * 32u * 32u * 4u;
            cpa16(ab + rowoff, A + (size_t)(bm + r) * K + k0 + lc * 4, 16);
            int m = bn + r;
            const float* ws = W + (size_t)(m < M ? m : 0) * K + k0 + lc * 4;
            cpa16(bb + rowoff, ws, (m < M) ? 16 : 0);
        }
    };

    issue(0); cpa_commit();
    if (KT > 1) issue(1);
    cpa_commit();

    for (int it = 0; it < KT; it++) {
        if (it + 2 < KT) issue(it + 2);
        cpa_commit();
        cpa_wait<2>();
        __syncthreads();

        const float* Asm = smf + (it % 3) * GSTAGE_F;
        const float* Bsm = Asm + 4096;

        #pragma unroll
        for (int ks = 0; ks < 4; ks++) {
            const int kb = ks * 8;
            float a[4][4], b[4][2];
            #pragma unroll
            for (int mt = 0; mt < 4; mt++) {
                int m0 = warp_m * 64 + mt * 16;
                a[mt][0] = Asm[gsw(m0 + g,     kb + tig)];
                a[mt][1] = Asm[gsw(m0 + g + 8, kb + tig)];
                a[mt][2] = Asm[gsw(m0 + g,     kb + tig + 4)];
                a[mt][3] = Asm[gsw(m0 + g + 8, kb + tig + 4)];
            }
            #pragma unroll
            for (int nt = 0; nt < 4; nt++) {
                int n0 = warp_n * 32 + nt * 8;
                b[nt][0] = f2tf32(Bsm[gsw(n0 + g, kb + tig)]);
                b[nt][1] = f2tf32(Bsm[gsw(n0 + g, kb + tig + 4)]);
            }
            #pragma unroll
            for (int mt = 0; mt < 4; mt++)
                #pragma unroll
                for (int nt = 0; nt < 4; nt++)
                    mma_tf32(acc[mt][nt], a[mt], b[nt]);
        }
        __syncthreads();
    }

    #pragma unroll
    for (int mt = 0; mt < 4; mt++) {
        #pragma unroll
        for (int nt = 0; nt < 4; nt++) {
            int col = bn + warp_n * 32 + nt * 8 + 2 * tig;
            #pragma unroll
            for (int rr = 0; rr < 2; rr++) {
                int row = bm + warp_m * 64 + mt * 16 + g + rr * 8;
                float v0 = acc[mt][nt][rr * 2 + 0];
                float v1 = acc[mt][nt][rr * 2 + 1];
                size_t idx = (size_t)row * M + col;
                if (S > 1) {
                    if (split == 0 && bias) { v0 += bias[col]; v1 += bias[col + 1]; }
                    atomicAdd(&C[idx],     v0);
                    atomicAdd(&C[idx + 1], v1);
                    continue;
                }
                if (bias) { v0 += bias[col]; if (col + 1 < M) v1 += bias[col + 1]; }
                if (gelu) {
                    float u = v0;
                    v0 = f2tf32(0.5f * u * (1.f + tanhf(0.7978845608028654f *
                                                 (u + 0.044715f * u * u * u))));
                    u = v1;
                    v1 = f2tf32(0.5f * u * (1.f + tanhf(0.7978845608028654f *
                                                 (u + 0.044715f * u * u * u))));
                } else if (rnd) {
                    v0 = f2tf32(v0);
                    v1 = f2tf32(v1);
                }
                if (col + 1 < M) {
                    if (res) { v0 += res[idx]; v1 += res[idx + 1]; }
                    C[idx]     = v0;
                    C[idx + 1] = v1;
                } else if (col < M) {
                    if (res) v0 += res[idx];
                    C[idx] = v0;
                }
            }
        }
    }
}

// ---------------------------------------------------------------------------
// Tensor-core flash attention (tf32 mma), cp.async double-buffered K/V.
// K/V arrive pre-rounded to tf32 (QKV GEMM epilogue) — HW truncation no-op.
// Causal masking specialized to the diagonal block (jt == qt) only.
// ---------------------------------------------------------------------------
#define ATQ 64
#define ATK 64
#define LOG2E 1.44269504088896f
#define ATTN_SMEM (5 * 4096 * 4)   // 81920 B

__device__ __forceinline__ int tswz(int r, int c) {
    return r * 64 + ((((c >> 2) ^ ((r + (r >> 4)) & 15))) << 2) + (c & 3);
}
__device__ __forceinline__ int vswz(int r, int c) {
    return r * 64 + ((((c >> 2) ^ ((r & 3) << 1))) << 2) + (c & 3);
}

__global__ __launch_bounds__(128)
void attn_kernel(const float* __restrict__ qkv, float* __restrict__ out) {
    extern __shared__ float sm[];
    float* Qs = sm;                       // [64][64] tswz

    const int qt = gridDim.x - 1 - blockIdx.x;   // heavy tiles first
    const int bh = blockIdx.y;
    const int b  = bh / NHEAD, h = bh % NHEAD;
    const int q0 = qt * ATQ;
    const int tid  = threadIdx.x;
    const int lane = tid & 31;
    const int wid  = tid >> 5;
    const int g    = lane >> 2;
    const int tig  = lane & 3;
    const int m0   = wid * 16;
    const size_t rstride = 3 * CDIM;
    const float qsc = 0.125f * LOG2E;
    const uint32_t sbase = smem_u32(sm);

    // ---- stage Q (scaled + tf32 RNA) ----
    #pragma unroll
    for (int i = 0; i < 8; i++) {
        int f = i * 128 + tid;
        int r = f >> 4, c4 = (f & 15) * 4;
        float4 v = *(const float4*)(qkv + (size_t)(b * TSEQ + q0 + r) * rstride
                                    + h * DHEAD + c4);
        v.x = f2tf32(v.x * qsc); v.y = f2tf32(v.y * qsc);
        v.z = f2tf32(v.z * qsc); v.w = f2tf32(v.w * qsc);
        *(float4*)&Qs[tswz(r, c4)] = v;
    }

    // cp.async K/V tile loader: buffer (jt&1)
    const int lr0 = tid >> 4;      // 0..7
    const int lch = tid & 15;      // 16B chunk in row
    auto issueKV = [&](int jt2) {
        if (jt2 > qt) return;
        const int jr = jt2 * ATK;
        const uint32_t kbase = sbase + (4096u + (uint32_t)(jt2 & 1) * 8192u) * 4u;
        const uint32_t vbase = kbase + 4096u * 4u;
        #pragma unroll
        for (int i = 0; i < 8; i++) {
            int r = lr0 + i * 8;
            const float* src = qkv + (size_t)(b * TSEQ + jr + r) * rstride
                               + h * DHEAD + lch * 4;
            uint32_t koff = (uint32_t)(r * 64 + ((lch ^ ((r + (r >> 4)) & 15)) << 2)) * 4u;
            uint32_t voff = (uint32_t)(r * 64 + ((lch ^ ((r & 3) << 1)) << 2)) * 4u;
            cpa16(kbase + koff, src + CDIM,     16);
            cpa16(vbase + voff, src + 2 * CDIM, 16);
        }
    };

    issueKV(0); cpa_commit();

    float mrow[2] = {-1e30f, -1e30f};
    float lrow[2] = {0.f, 0.f};
    float O[8][4];
    #pragma unroll
    for (int nt = 0; nt < 8; nt++)
        #pragma unroll
        for (int r = 0; r < 4; r++) O[nt][r] = 0.f;

    const int src1 = (g << 2) | (tig >> 1);
    const int src2 = src1 + 2;
    const bool odd = (tig & 1);

    for (int jt = 0; jt <= qt; jt++) {
        issueKV(jt + 1); cpa_commit();
        cpa_wait<1>();
        __syncthreads();

        const float* Ks = sm + 4096 + (jt & 1) * 8192;
        const float* Vs = Ks + 4096;

        // ---- GEMM1: S = Q K^T  (warp tile 16 x 64) ----
        float s[8][4];
        #pragma unroll
        for (int nt = 0; nt < 8; nt++)
            #pragma unroll
            for (int r = 0; r < 4; r++) s[nt][r] = 0.f;

        #pragma unroll
        for (int ks = 0; ks < 8; ks++) {
            const int kb = ks * 8;
            float a[4];
            a[0] = Qs[tswz(m0 + g,     kb + tig)];
            a[1] = Qs[tswz(m0 + g + 8, kb + tig)];
            a[2] = Qs[tswz(m0 + g,     kb + tig + 4)];
            a[3] = Qs[tswz(m0 + g + 8, kb + tig + 4)];
            #pragma unroll
            for (int nt = 0; nt < 8; nt++) {
                float bb[2];
                bb[0] = Ks[tswz(nt * 8 + g, kb + tig)];
                bb[1] = Ks[tswz(nt * 8 + g, kb + tig + 4)];
                mma_tf32(s[nt], a, bb);
            }
        }

        // ---- causal mask: only the diagonal block needs it ----
        if (jt == qt) {
            const int r0 = m0 + g, r1 = r0 + 8;   // local rows (q0 == jb here)
            #pragma unroll
            for (int nt = 0; nt < 8; nt++) {
                int c0 = nt * 8 + 2 * tig;
                if (c0     > r0) s[nt][0] = -1e30f;
                if (c0 + 1 > r0) s[nt][1] = -1e30f;
                if (c0     > r1) s[nt][2] = -1e30f;
                if (c0 + 1 > r1) s[nt][3] = -1e30f;
            }
        }

        // ---- online softmax ----
        float rx0 = -1e30f, rx1 = -1e30f;
        #pragma unroll
        for (int nt = 0; nt < 8; nt++) {
            rx0 = fmaxf(rx0, fmaxf(s[nt][0], s[nt][1]));
            rx1 = fmaxf(rx1, fmaxf(s[nt][2], s[nt][3]));
        }
        rx0 = fmaxf(rx0, __shfl_xor_sync(~0u, rx0, 1));
        rx0 = fmaxf(rx0, __shfl_xor_sync(~0u, rx0, 2));
        rx1 = fmaxf(rx1, __shfl_xor_sync(~0u, rx1, 1));
        rx1 = fmaxf(rx1, __shfl_xor_sync(~0u, rx1, 2));

        float mn0 = fmaxf(mrow[0], rx0);
        float mn1 = fmaxf(mrow[1], rx1);
        float fac0 = exp2f(mrow[0] - mn0);
        float fac1 = exp2f(mrow[1] - mn1);
        float ps0 = 0.f, ps1 = 0.f;
        #pragma unroll
        for (int nt = 0; nt < 8; nt++) {
            float p0 = f2tf32(exp2f(s[nt][0] - mn0));
            float p1 = f2tf32(exp2f(s[nt][1] - mn0));
            float p2 = f2tf32(exp2f(s[nt][2] - mn1));
            float p3 = f2tf32(exp2f(s[nt][3] - mn1));
            s[nt][0] = p0; s[nt][1] = p1; s[nt][2] = p2; s[nt][3] = p3;
            ps0 += p0 + p1; ps1 += p2 + p3;
        }
        ps0 += __shfl_xor_sync(~0u, ps0, 1);
        ps0 += __shfl_xor_sync(~0u, ps0, 2);
        ps1 += __shfl_xor_sync(~0u, ps1, 1);
        ps1 += __shfl_xor_sync(~0u, ps1, 2);
        lrow[0] = lrow[0] * fac0 + ps0;
        lrow[1] = lrow[1] * fac1 + ps1;
        mrow[0] = mn0; mrow[1] = mn1;

        #pragma unroll
        for (int nt = 0; nt < 8; nt++) {
            O[nt][0] *= fac0; O[nt][1] *= fac0;
            O[nt][2] *= fac1; O[nt][3] *= fac1;
        }

        // ---- GEMM2: O += P V  (A-frags via quad shuffles; B from vswz V) ----
        #pragma unroll
        for (int ks = 0; ks < 8; ks++) {
            float v0 = __shfl_sync(~0u, s[ks][0], src1);
            float v1 = __shfl_sync(~0u, s[ks][1], src1);
            float v2 = __shfl_sync(~0u, s[ks][2], src1);
            float v3 = __shfl_sync(~0u, s[ks][3], src1);
            float w0 = __shfl_sync(~0u, s[ks][0], src2);
            float w1 = __shfl_sync(~0u, s[ks][1], src2);
            float w2 = __shfl_sync(~0u, s[ks][2], src2);
            float w3 = __shfl_sync(~0u, s[ks][3], src2);
            float a[4];
            a[0] = odd ? v1 : v0;
            a[1] = odd ? v3 : v2;
            a[2] = odd ? w1 : w0;
            a[3] = odd ? w3 : w2;
            const int kb = ks * 8;
            #pragma unroll
            for (int nt = 0; nt < 8; nt++) {
                float bb[2];
                bb[0] = Vs[vswz(kb + tig,     nt * 8 + g)];
                bb[1] = Vs[vswz(kb + tig + 4, nt * 8 + g)];
                mma_tf32(O[nt], a, bb);
            }
        }
        __syncthreads();   // compute done before buffer (jt&1) is overwritten
    }

    float inv0 = 1.f / lrow[0];
    float inv1 = 1.f / lrow[1];
    float* o0 = out + (size_t)(b * TSEQ + q0 + m0 + g) * CDIM + h * DHEAD;
    float* o1 = o0 + 8 * CDIM;
    #pragma unroll
    for (int nt = 0; nt < 8; nt++) {
        int c = nt * 8 + 2 * tig;
        float2 u0 = make_float2(f2tf32(O[nt][0] * inv0), f2tf32(O[nt][1] * inv0));
        float2 u1 = make_float2(f2tf32(O[nt][2] * inv1), f2tf32(O[nt][3] * inv1));
        *(float2*)(o0 + c) = u0;
        *(float2*)(o1 + c) = u1;
    }
}

// ---------------------------------------------------------------------------
// Launcher
// ---------------------------------------------------------------------------
extern "C" void kernel_launch(void* const* d_in, const int* in_sizes, int n_in,
                              void* d_out, int out_size) {
    const int*   tokens    = (const int*)  d_in[0];
    const float* tok_embed = (const float*)d_in[1];
    const float* pos_embed = (const float*)d_in[2];
    const float* ln1_w     = (const float*)d_in[3];
    const float* ln1_b     = (const float*)d_in[4];
    const float* qkv_w     = (const float*)d_in[5];
    const float* qkv_b     = (const float*)d_in[6];
    const float* proj_w    = (const float*)d_in[7];
    const float* proj_b    = (const float*)d_in[8];
    const float* ln2_w     = (const float*)d_in[9];
    const float* ln2_b     = (const float*)d_in[10];
    const float* fc_w      = (const float*)d_in[11];
    const float* fc_b      = (const float*)d_in[12];
    const float* fc2_w     = (const float*)d_in[13];
    const float* fc2_b     = (const float*)d_in[14];
    const float* lnf_w     = (const float*)d_in[15];
    const float* lnf_b     = (const float*)d_in[16];
    float* logits = (float*)d_out;

    float *x, *h, *qkv, *att, *ffn;
    cudaGetSymbolAddress((void**)&x,   g_x);
    cudaGetSymbolAddress((void**)&h,   g_h);
    cudaGetSymbolAddress((void**)&qkv, g_qkv);
    cudaGetSymbolAddress((void**)&att, g_att);
    cudaGetSymbolAddress((void**)&ffn, g_ffn);

    cudaFuncSetAttribute(attn_kernel,
                         cudaFuncAttributeMaxDynamicSharedMemorySize, ATTN_SMEM);
    cudaFuncSetAttribute(gemm_tf32_kernel,
                         cudaFuncAttributeMaxDynamicSharedMemorySize, GSMEM_BYTES);

    embed_kernel<<<NROW, 256>>>(tokens, tok_embed, pos_embed, x);

    const int NB = NROW / 128;   // 16 row-blocks
    for (int l = 0; l < NLAYER; l++) {
        const float* l1w = ln1_w  + (size_t)l * CDIM;
        const float* l1b = ln1_b  + (size_t)l * CDIM;
        const float* qw  = qkv_w  + (size_t)l * 3 * CDIM * CDIM;
        const float* qb  = qkv_b  + (size_t)l * 3 * CDIM;
        const float* pw  = proj_w + (size_t)l * CDIM * CDIM;
        const float* pb  = proj_b + (size_t)l * CDIM;
        const float* l2w = ln2_w  + (size_t)l * CDIM;
        const float* l2b = ln2_b  + (size_t)l * CDIM;
        const float* fw  = fc_w   + (size_t)l * FFDIM * CDIM;
        const float* fb  = fc_b   + (size_t)l * FFDIM;
        const float* f2w = fc2_w  + (size_t)l * CDIM * FFDIM;
        const float* f2b = fc2_b  + (size_t)l * CDIM;

        ln_kernel<<<NROW / 8, 256>>>(x, l1w, l1b, h);
        // qkv: rnd=1 so attention's K/V are exact tf32 values
        gemm_tf32_kernel<<<dim3(3 * CDIM / 128, NB), 256, GSMEM_BYTES>>>(
            h, qw, qb, nullptr, qkv, NROW, 3 * CDIM, CDIM, 0, 1);
        attn_kernel<<<dim3(TSEQ / ATQ, BSZ * NHEAD), 128, ATTN_SMEM>>>(qkv, att);
        // proj: split-K=3, x += att @ pw^T + pb (atomic, in place)
        gemm_tf32_kernel<<<dim3(CDIM / 128, NB, 3), 256, GSMEM_BYTES>>>(
            att, pw, pb, nullptr, x, NROW, CDIM, CDIM, 0, 0);
        ln_kernel<<<NROW / 8, 256>>>(x, l2w, l2b, h);
        gemm_tf32_kernel<<<dim3(FFDIM / 128, NB), 256, GSMEM_BYTES>>>(
            h, fw, fb, nullptr, ffn, NROW, FFDIM, CDIM, 1, 0);
        // fc2: split-K=3, x += ffn @ f2w^T + f2b (atomic, in place)
        gemm_tf32_kernel<<<dim3(CDIM / 128, NB, 3), 256, GSMEM_BYTES>>>(
            ffn, f2w, f2b, nullptr, x, NROW, CDIM, FFDIM, 0, 0);
    }

    ln_kernel<<<NROW / 8, 256>>>(x, lnf_w, lnf_b, h);
    gemm_tf32_kernel<<<dim3((VOCAB + 127) / 128, NB), 256, GSMEM_BYTES>>>(
        h, tok_embed, nullptr, nullptr, logits, NROW, VOCAB, CDIM, 0, 0);
}

// round 14
// speedup vs baseline: 1.2425x; 1.0386x over previous
#include <cuda_runtime.h>
#include <math.h>
#include <stdint.h>

// GPT-2 small config
#define BSZ   2
#define TSEQ  1024
#define CDIM  768
#define FFDIM 3072
#define NHEAD 12
#define NLAYER 12
#define DHEAD 64
#define VOCAB 50257
#define NROW  (BSZ * TSEQ)   // 2048

// ---------------------------------------------------------------------------
// Scratch (device globals — no allocation allowed)
// ---------------------------------------------------------------------------
__device__ float g_x  [NROW * CDIM];
__device__ float g_h  [NROW * CDIM];
__device__ float g_qkv[NROW * 3 * CDIM];
__device__ float g_att[NROW * CDIM];
__device__ float g_ffn[NROW * FFDIM];

// ---------------------------------------------------------------------------
// Helpers
// ---------------------------------------------------------------------------
__device__ __forceinline__ float f2tf32(float x) {
    asm("cvt.rna.tf32.f32 %0, %0;" : "+f"(x));
    return x;
}

__device__ __forceinline__ void mma_tf32(float (&d)[4],
                                         const float (&a)[4],
                                         const float (&b)[2]) {
    asm volatile(
        "mma.sync.aligned.m16n8k8.row.col.f32.tf32.tf32.f32 "
        "{%0,%1,%2,%3}, {%4,%5,%6,%7}, {%8,%9}, {%0,%1,%2,%3};\n"
        : "+f"(d[0]), "+f"(d[1]), "+f"(d[2]), "+f"(d[3])
        : "r"(__float_as_uint(a[0])), "r"(__float_as_uint(a[1])),
          "r"(__float_as_uint(a[2])), "r"(__float_as_uint(a[3])),
          "r"(__float_as_uint(b[0])), "r"(__float_as_uint(b[1])));
}

__device__ __forceinline__ uint32_t smem_u32(const void* p) {
    uint32_t a;
    asm("{ .reg .u64 t; cvta.to.shared.u64 t, %1; cvt.u32.u64 %0, t; }"
        : "=r"(a) : "l"(p));
    return a;
}

__device__ __forceinline__ void cpa16(uint32_t dst, const float* src, int sz) {
    asm volatile("cp.async.cg.shared.global [%0], [%1], 16, %2;"
                 :: "r"(dst), "l"(src), "r"(sz));
}
__device__ __forceinline__ void cpa_commit() {
    asm volatile("cp.async.commit_group;" ::: "memory");
}
template <int N>
__device__ __forceinline__ void cpa_wait() {
    asm volatile("cp.async.wait_group %0;" :: "n"(N) : "memory");
}

// ---------------------------------------------------------------------------
// Embedding
// ---------------------------------------------------------------------------
__global__ void embed_kernel(const int* __restrict__ tokens,
                             const float* __restrict__ tok,
                             const float* __restrict__ pos,
                             float* __restrict__ x) {
    int n = blockIdx.x;
    int t = n % TSEQ;
    int tk = tokens[n];
    const float* tr = tok + (size_t)tk * CDIM;
    const float* pr = pos + (size_t)t * CDIM;
    float* xr = x + (size_t)n * CDIM;
    for (int c = threadIdx.x; c < CDIM; c += blockDim.x)
        xr[c] = tr[c] + pr[c];
}

// ---------------------------------------------------------------------------
// LayerNorm: warp per row, 8 rows/block, row cached in regs. tf32-rounded out.
// ---------------------------------------------------------------------------
__global__ __launch_bounds__(256)
void ln_kernel(const float* __restrict__ x,
               const float* __restrict__ w,
               const float* __restrict__ b,
               float* __restrict__ out) {
    const int lane = threadIdx.x & 31;
    const int wrp  = threadIdx.x >> 5;
    const int n = blockIdx.x * 8 + wrp;
    const float* xr = x + (size_t)n * CDIM;

    float4 v[6];
    float s = 0.f, s2 = 0.f;
    #pragma unroll
    for (int i = 0; i < 6; i++) {
        v[i] = *(const float4*)(xr + i * 128 + lane * 4);
        s  += v[i].x + v[i].y + v[i].z + v[i].w;
        s2 += v[i].x * v[i].x + v[i].y * v[i].y
            + v[i].z * v[i].z + v[i].w * v[i].w;
    }
    #pragma unroll
    for (int o = 16; o; o >>= 1) {
        s  += __shfl_xor_sync(~0u, s,  o);
        s2 += __shfl_xor_sync(~0u, s2, o);
    }
    float m = s / CDIM;
    float var = s2 / CDIM - m * m;
    float r = rsqrtf(var + 1e-5f);

    float* orow = out + (size_t)n * CDIM;
    #pragma unroll
    for (int i = 0; i < 6; i++) {
        int c = i * 128 + lane * 4;
        float4 wv = *(const float4*)(w + c);
        float4 bv = *(const float4*)(b + c);
        float4 o;
        o.x = f2tf32((v[i].x - m) * r * wv.x + bv.x);
        o.y = f2tf32((v[i].y - m) * r * wv.y + bv.y);
        o.z = f2tf32((v[i].z - m) * r * wv.z + bv.z);
        o.w = f2tf32((v[i].w - m) * r * wv.w + bv.w);
        *(float4*)(orow + c) = o;
    }
}

// ---------------------------------------------------------------------------
// TF32 NT GEMM, cp.async 2-stage pipeline (64KB smem), 2 blocks/SM.
// BK=32, optional split-K. rnd=1: tf32-round plain-store outputs (QKV GEMM).
// ---------------------------------------------------------------------------
#define GSTAGE_F 8192
#define GSMEM_BYTES (2 * GSTAGE_F * 4)   // 64 KB

__device__ __forceinline__ int gsw(int r, int k) {
    return r * 32 + (((k >> 2) ^ (r & 7)) << 2) + (k & 3);
}

__global__ __launch_bounds__(256, 2)
void gemm_tf32_kernel(const float* __restrict__ A, const float* __restrict__ W,
                      const float* __restrict__ bias, const float* __restrict__ res,
                      float* __restrict__ C, int N, int M, int K, int gelu,
                      int rnd) {
    extern __shared__ __align__(16) float smf[];

    const int tid  = threadIdx.x;
    const int lane = tid & 31;
    const int wid  = tid >> 5;
    const int g    = lane >> 2;
    const int tig  = lane & 3;
    const int warp_m = wid >> 2;
    const int warp_n = wid & 3;
    const int bm = blockIdx.y * 128;
    const int bn = blockIdx.x * 128;
    const int S     = gridDim.z;
    const int split = blockIdx.z;
    const int Ks     = K / S;
    const int k0base = split * Ks;
    const uint32_t sbase = smem_u32(smf);

    const int lr = tid >> 3;
    const int lc = tid & 7;
    const uint32_t soff = (uint32_t)(lr * 32 + ((lc ^ (lr & 7)) << 2)) * 4u;

    float acc[4][4][4];
    #pragma unroll
    for (int mt = 0; mt < 4; mt++)
        #pragma unroll
        for (int nt = 0; nt < 4; nt++)
            #pragma unroll
            for (int r = 0; r < 4; r++) acc[mt][nt][r] = 0.f;

    const int KT = Ks / 32;

    auto issue = [&](int j) {
        const int k0 = k0base + j * 32;
        const uint32_t ab = sbase + (uint32_t)(j & 1) * GSTAGE_F * 4u;
        const uint32_t bb = ab + 4096u * 4u;
        #pragma unroll
        for (int i = 0; i < 4; i++) {
            int r = lr + i * 32;
            uint32_t rowoff = soff + (uint32_t)i * 32u * 32u * 4u;
            cpa16(ab + rowoff, A + (size_t)(bm + r) * K + k0 + lc * 4, 16);
            int m = bn + r;
            const float* ws = W + (size_t)(m < M ? m : 0) * K + k0 + lc * 4;
            cpa16(bb + rowoff, ws, (m < M) ? 16 : 0);
        }
    };

    issue(0); cpa_commit();

    for (int it = 0; it < KT; it++) {
        if (it + 1 < KT) issue(it + 1);
        cpa_commit();
        cpa_wait<1>();
        __syncthreads();

        const float* Asm = smf + (it & 1) * GSTAGE_F;
        const float* Bsm = Asm + 4096;

        #pragma unroll
        for (int ks = 0; ks < 4; ks++) {
            const int kb = ks * 8;
            float a[4][4], b[4][2];
            #pragma unroll
            for (int mt = 0; mt < 4; mt++) {
                int m0 = warp_m * 64 + mt * 16;
                a[mt][0] = Asm[gsw(m0 + g,     kb + tig)];
                a[mt][1] = Asm[gsw(m0 + g + 8, kb + tig)];
                a[mt][2] = Asm[gsw(m0 + g,     kb + tig + 4)];
                a[mt][3] = Asm[gsw(m0 + g + 8, kb + tig + 4)];
            }
            #pragma unroll
            for (int nt = 0; nt < 4; nt++) {
                int n0 = warp_n * 32 + nt * 8;
                b[nt][0] = f2tf32(Bsm[gsw(n0 + g, kb + tig)]);
                b[nt][1] = f2tf32(Bsm[gsw(n0 + g, kb + tig + 4)]);
            }
            #pragma unroll
            for (int mt = 0; mt < 4; mt++)
                #pragma unroll
                for (int nt = 0; nt < 4; nt++)
                    mma_tf32(acc[mt][nt], a[mt], b[nt]);
        }
        __syncthreads();
    }

    #pragma unroll
    for (int mt = 0; mt < 4; mt++) {
        #pragma unroll
        for (int nt = 0; nt < 4; nt++) {
            int col = bn + warp_n * 32 + nt * 8 + 2 * tig;
            #pragma unroll
            for (int rr = 0; rr < 2; rr++) {
                int row = bm + warp_m * 64 + mt * 16 + g + rr * 8;
                float v0 = acc[mt][nt][rr * 2 + 0];
                float v1 = acc[mt][nt][rr * 2 + 1];
                size_t idx = (size_t)row * M + col;
                if (S > 1) {
                    if (split == 0 && bias) { v0 += bias[col]; v1 += bias[col + 1]; }
                    atomicAdd(&C[idx],     v0);
                    atomicAdd(&C[idx + 1], v1);
                    continue;
                }
                if (bias) { v0 += bias[col]; if (col + 1 < M) v1 += bias[col + 1]; }
                if (gelu) {
                    float u = v0;
                    v0 = f2tf32(0.5f * u * (1.f + tanhf(0.7978845608028654f *
                                                 (u + 0.044715f * u * u * u))));
                    u = v1;
                    v1 = f2tf32(0.5f * u * (1.f + tanhf(0.7978845608028654f *
                                                 (u + 0.044715f * u * u * u))));
                } else if (rnd) {
                    v0 = f2tf32(v0);
                    v1 = f2tf32(v1);
                }
                if (col + 1 < M) {
                    if (res) { v0 += res[idx]; v1 += res[idx + 1]; }
                    C[idx]     = v0;
                    C[idx + 1] = v1;
                } else if (col < M) {
                    if (res) v0 += res[idx];
                    C[idx] = v0;
                }
            }
        }
    }
}

// ---------------------------------------------------------------------------
// Tensor-core flash attention (tf32 mma), cp.async double-buffered K/V.
// (unchanged from R12 — validated at 55.8us/launch, rel_err 8.33e-4)
// ---------------------------------------------------------------------------
#define ATQ 64
#define ATK 64
#define LOG2E 1.44269504088896f
#define ATTN_SMEM (5 * 4096 * 4)   // 81920 B

__device__ __forceinline__ int tswz(int r, int c) {
    return r * 64 + ((((c >> 2) ^ ((r + (r >> 4)) & 15))) << 2) + (c & 3);
}
__device__ __forceinline__ int vswz(int r, int c) {
    return r * 64 + ((((c >> 2) ^ ((r & 3) << 1))) << 2) + (c & 3);
}

__global__ __launch_bounds__(128)
void attn_kernel(const float* __restrict__ qkv, float* __restrict__ out) {
    extern __shared__ float sm[];
    float* Qs = sm;                       // [64][64] tswz

    const int qt = gridDim.x - 1 - blockIdx.x;   // heavy tiles first
    const int bh = blockIdx.y;
    const int b  = bh / NHEAD, h = bh % NHEAD;
    const int q0 = qt * ATQ;
    const int tid  = threadIdx.x;
    const int lane = tid & 31;
    const int wid  = tid >> 5;
    const int g    = lane >> 2;
    const int tig  = lane & 3;
    const int m0   = wid * 16;
    const size_t rstride = 3 * CDIM;
    const float qsc = 0.125f * LOG2E;
    const uint32_t sbase = smem_u32(sm);

    // ---- stage Q (scaled + tf32 RNA) ----
    #pragma unroll
    for (int i = 0; i < 8; i++) {
        int f = i * 128 + tid;
        int r = f >> 4, c4 = (f & 15) * 4;
        float4 v = *(const float4*)(qkv + (size_t)(b * TSEQ + q0 + r) * rstride
                                    + h * DHEAD + c4);
        v.x = f2tf32(v.x * qsc); v.y = f2tf32(v.y * qsc);
        v.z = f2tf32(v.z * qsc); v.w = f2tf32(v.w * qsc);
        *(float4*)&Qs[tswz(r, c4)] = v;
    }

    // cp.async K/V tile loader: buffer (jt&1)
    const int lr0 = tid >> 4;      // 0..7
    const int lch = tid & 15;      // 16B chunk in row
    auto issueKV = [&](int jt2) {
        if (jt2 > qt) return;
        const int jr = jt2 * ATK;
        const uint32_t kbase = sbase + (4096u + (uint32_t)(jt2 & 1) * 8192u) * 4u;
        const uint32_t vbase = kbase + 4096u * 4u;
        #pragma unroll
        for (int i = 0; i < 8; i++) {
            int r = lr0 + i * 8;
            const float* src = qkv + (size_t)(b * TSEQ + jr + r) * rstride
                               + h * DHEAD + lch * 4;
            uint32_t koff = (uint32_t)(r * 64 + ((lch ^ ((r + (r >> 4)) & 15)) << 2)) * 4u;
            uint32_t voff = (uint32_t)(r * 64 + ((lch ^ ((r & 3) << 1)) << 2)) * 4u;
            cpa16(kbase + koff, src + CDIM,     16);
            cpa16(vbase + voff, src + 2 * CDIM, 16);
        }
    };

    issueKV(0); cpa_commit();

    float mrow[2] = {-1e30f, -1e30f};
    float lrow[2] = {0.f, 0.f};
    float O[8][4];
    #pragma unroll
    for (int nt = 0; nt < 8; nt++)
        #pragma unroll
        for (int r = 0; r < 4; r++) O[nt][r] = 0.f;

    const int src1 = (g << 2) | (tig >> 1);
    const int src2 = src1 + 2;
    const bool odd = (tig & 1);

    for (int jt = 0; jt <= qt; jt++) {
        issueKV(jt + 1); cpa_commit();
        cpa_wait<1>();
        __syncthreads();

        const float* Ks = sm + 4096 + (jt & 1) * 8192;
        const float* Vs = Ks + 4096;

        // ---- GEMM1: S = Q K^T  (warp tile 16 x 64) ----
        float s[8][4];
        #pragma unroll
        for (int nt = 0; nt < 8; nt++)
            #pragma unroll
            for (int r = 0; r < 4; r++) s[nt][r] = 0.f;

        #pragma unroll
        for (int ks = 0; ks < 8; ks++) {
            const int kb = ks * 8;
            float a[4];
            a[0] = Qs[tswz(m0 + g,     kb + tig)];
            a[1] = Qs[tswz(m0 + g + 8, kb + tig)];
            a[2] = Qs[tswz(m0 + g,     kb + tig + 4)];
            a[3] = Qs[tswz(m0 + g + 8, kb + tig + 4)];
            #pragma unroll
            for (int nt = 0; nt < 8; nt++) {
                float bb[2];
                bb[0] = Ks[tswz(nt * 8 + g, kb + tig)];
                bb[1] = Ks[tswz(nt * 8 + g, kb + tig + 4)];
                mma_tf32(s[nt], a, bb);
            }
        }

        // ---- causal mask: only the diagonal block needs it ----
        if (jt == qt) {
            const int r0 = m0 + g, r1 = r0 + 8;   // local rows (q0 == jb here)
            #pragma unroll
            for (int nt = 0; nt < 8; nt++) {
                int c0 = nt * 8 + 2 * tig;
                if (c0     > r0) s[nt][0] = -1e30f;
                if (c0 + 1 > r0) s[nt][1] = -1e30f;
                if (c0     > r1) s[nt][2] = -1e30f;
                if (c0 + 1 > r1) s[nt][3] = -1e30f;
            }
        }

        // ---- online softmax ----
        float rx0 = -1e30f, rx1 = -1e30f;
        #pragma unroll
        for (int nt = 0; nt < 8; nt++) {
            rx0 = fmaxf(rx0, fmaxf(s[nt][0], s[nt][1]));
            rx1 = fmaxf(rx1, fmaxf(s[nt][2], s[nt][3]));
        }
        rx0 = fmaxf(rx0, __shfl_xor_sync(~0u, rx0, 1));
        rx0 = fmaxf(rx0, __shfl_xor_sync(~0u, rx0, 2));
        rx1 = fmaxf(rx1, __shfl_xor_sync(~0u, rx1, 1));
        rx1 = fmaxf(rx1, __shfl_xor_sync(~0u, rx1, 2));

        float mn0 = fmaxf(mrow[0], rx0);
        float mn1 = fmaxf(mrow[1], rx1);
        float fac0 = exp2f(mrow[0] - mn0);
        float fac1 = exp2f(mrow[1] - mn1);
        float ps0 = 0.f, ps1 = 0.f;
        #pragma unroll
        for (int nt = 0; nt < 8; nt++) {
            float p0 = f2tf32(exp2f(s[nt][0] - mn0));
            float p1 = f2tf32(exp2f(s[nt][1] - mn0));
            float p2 = f2tf32(exp2f(s[nt][2] - mn1));
            float p3 = f2tf32(exp2f(s[nt][3] - mn1));
            s[nt][0] = p0; s[nt][1] = p1; s[nt][2] = p2; s[nt][3] = p3;
            ps0 += p0 + p1; ps1 += p2 + p3;
        }
        ps0 += __shfl_xor_sync(~0u, ps0, 1);
        ps0 += __shfl_xor_sync(~0u, ps0, 2);
        ps1 += __shfl_xor_sync(~0u, ps1, 1);
        ps1 += __shfl_xor_sync(~0u, ps1, 2);
        lrow[0] = lrow[0] * fac0 + ps0;
        lrow[1] = lrow[1] * fac1 + ps1;
        mrow[0] = mn0; mrow[1] = mn1;

        #pragma unroll
        for (int nt = 0; nt < 8; nt++) {
            O[nt][0] *= fac0; O[nt][1] *= fac0;
            O[nt][2] *= fac1; O[nt][3] *= fac1;
        }

        // ---- GEMM2: O += P V  (A-frags via quad shuffles; B from vswz V) ----
        #pragma unroll
        for (int ks = 0; ks < 8; ks++) {
            float v0 = __shfl_sync(~0u, s[ks][0], src1);
            float v1 = __shfl_sync(~0u, s[ks][1], src1);
            float v2 = __shfl_sync(~0u, s[ks][2], src1);
            float v3 = __shfl_sync(~0u, s[ks][3], src1);
            float w0 = __shfl_sync(~0u, s[ks][0], src2);
            float w1 = __shfl_sync(~0u, s[ks][1], src2);
            float w2 = __shfl_sync(~0u, s[ks][2], src2);
            float w3 = __shfl_sync(~0u, s[ks][3], src2);
            float a[4];
            a[0] = odd ? v1 : v0;
            a[1] = odd ? v3 : v2;
            a[2] = odd ? w1 : w0;
            a[3] = odd ? w3 : w2;
            const int kb = ks * 8;
            #pragma unroll
            for (int nt = 0; nt < 8; nt++) {
                float bb[2];
                bb[0] = Vs[vswz(kb + tig,     nt * 8 + g)];
                bb[1] = Vs[vswz(kb + tig + 4, nt * 8 + g)];
                mma_tf32(O[nt], a, bb);
            }
        }
        __syncthreads();   // compute done before buffer (jt&1) is overwritten
    }

    float inv0 = 1.f / lrow[0];
    float inv1 = 1.f / lrow[1];
    float* o0 = out + (size_t)(b * TSEQ + q0 + m0 + g) * CDIM + h * DHEAD;
    float* o1 = o0 + 8 * CDIM;
    #pragma unroll
    for (int nt = 0; nt < 8; nt++) {
        int c = nt * 8 + 2 * tig;
        float2 u0 = make_float2(f2tf32(O[nt][0] * inv0), f2tf32(O[nt][1] * inv0));
        float2 u1 = make_float2(f2tf32(O[nt][2] * inv1), f2tf32(O[nt][3] * inv1));
        *(float2*)(o0 + c) = u0;
        *(float2*)(o1 + c) = u1;
    }
}

// ---------------------------------------------------------------------------
// Launcher
// ---------------------------------------------------------------------------
extern "C" void kernel_launch(void* const* d_in, const int* in_sizes, int n_in,
                              void* d_out, int out_size) {
    const int*   tokens    = (const int*)  d_in[0];
    const float* tok_embed = (const float*)d_in[1];
    const float* pos_embed = (const float*)d_in[2];
    const float* ln1_w     = (const float*)d_in[3];
    const float* ln1_b     = (const float*)d_in[4];
    const float* qkv_w     = (const float*)d_in[5];
    const float* qkv_b     = (const float*)d_in[6];
    const float* proj_w    = (const float*)d_in[7];
    const float* proj_b    = (const float*)d_in[8];
    const float* ln2_w     = (const float*)d_in[9];
    const float* ln2_b     = (const float*)d_in[10];
    const float* fc_w      = (const float*)d_in[11];
    const float* fc_b      = (const float*)d_in[12];
    const float* fc2_w     = (const float*)d_in[13];
    const float* fc2_b     = (const float*)d_in[14];
    const float* lnf_w     = (const float*)d_in[15];
    const float* lnf_b     = (const float*)d_in[16];
    float* logits = (float*)d_out;

    float *x, *h, *qkv, *att, *ffn;
    cudaGetSymbolAddress((void**)&x,   g_x);
    cudaGetSymbolAddress((void**)&h,   g_h);
    cudaGetSymbolAddress((void**)&qkv, g_qkv);
    cudaGetSymbolAddress((void**)&att, g_att);
    cudaGetSymbolAddress((void**)&ffn, g_ffn);

    cudaFuncSetAttribute(attn_kernel,
                         cudaFuncAttributeMaxDynamicSharedMemorySize, ATTN_SMEM);
    cudaFuncSetAttribute(gemm_tf32_kernel,
                         cudaFuncAttributeMaxDynamicSharedMemorySize, GSMEM_BYTES);

    embed_kernel<<<NROW, 256>>>(tokens, tok_embed, pos_embed, x);

    const int NB = NROW / 128;   // 16 row-blocks
    for (int l = 0; l < NLAYER; l++) {
        const float* l1w = ln1_w  + (size_t)l * CDIM;
        const float* l1b = ln1_b  + (size_t)l * CDIM;
        const float* qw  = qkv_w  + (size_t)l * 3 * CDIM * CDIM;
        const float* qb  = qkv_b  + (size_t)l * 3 * CDIM;
        const float* pw  = proj_w + (size_t)l * CDIM * CDIM;
        const float* pb  = proj_b + (size_t)l * CDIM;
        const float* l2w = ln2_w  + (size_t)l * CDIM;
        const float* l2b = ln2_b  + (size_t)l * CDIM;
        const float* fw  = fc_w   + (size_t)l * FFDIM * CDIM;
        const float* fb  = fc_b   + (size_t)l * FFDIM;
        const float* f2w = fc2_w  + (size_t)l * CDIM * FFDIM;
        const float* f2b = fc2_b  + (size_t)l * CDIM;

        ln_kernel<<<NROW / 8, 256>>>(x, l1w, l1b, h);
        // qkv: rnd=1 so attention's K/V are exact tf32 values
        gemm_tf32_kernel<<<dim3(3 * CDIM / 128, NB), 256, GSMEM_BYTES>>>(
            h, qw, qb, nullptr, qkv, NROW, 3 * CDIM, CDIM, 0, 1);
        attn_kernel<<<dim3(TSEQ / ATQ, BSZ * NHEAD), 128, ATTN_SMEM>>>(qkv, att);
        // proj: split-K=3, x += att @ pw^T + pb (atomic, in place)
        gemm_tf32_kernel<<<dim3(CDIM / 128, NB, 3), 256, GSMEM_BYTES>>>(
            att, pw, pb, nullptr, x, NROW, CDIM, CDIM, 0, 0);
        ln_kernel<<<NROW / 8, 256>>>(x, l2w, l2b, h);
        gemm_tf32_kernel<<<dim3(FFDIM / 128, NB), 256, GSMEM_BYTES>>>(
            h, fw, fb, nullptr, ffn, NROW, FFDIM, CDIM, 1, 0);
        // fc2: split-K=3, x += ffn @ f2w^T + f2b (atomic, in place)
        gemm_tf32_kernel<<<dim3(CDIM / 128, NB, 3), 256, GSMEM_BYTES>>>(
            ffn, f2w, f2b, nullptr, x, NROW, CDIM, FFDIM, 0, 0);
    }

    ln_kernel<<<NROW / 8, 256>>>(x, lnf_w, lnf_b, h);
    gemm_tf32_kernel<<<dim3((VOCAB + 127) / 128, NB), 256, GSMEM_BYTES>>>(
        h, tok_embed, nullptr, nullptr, logits, NROW, VOCAB, CDIM, 0, 0);
}

// round 15
// speedup vs baseline: 1.2455x; 1.0024x over previous
#include <cuda_runtime.h>
#include <math.h>
#include <stdint.h>

// GPT-2 small config
#define BSZ   2
#define TSEQ  1024
#define CDIM  768
#define FFDIM 3072
#define NHEAD 12
#define NLAYER 12
#define DHEAD 64
#define VOCAB 50257
#define NROW  (BSZ * TSEQ)   // 2048

// ---------------------------------------------------------------------------
// Scratch (device globals — no allocation allowed)
// ---------------------------------------------------------------------------
__device__ float g_x  [NROW * CDIM];
__device__ float g_h  [NROW * CDIM];
__device__ float g_qkv[NROW * 3 * CDIM];
__device__ float g_att[NROW * CDIM];
__device__ float g_ffn[NROW * FFDIM];

// ---------------------------------------------------------------------------
// Helpers
// ---------------------------------------------------------------------------
__device__ __forceinline__ float f2tf32(float x) {
    asm("cvt.rna.tf32.f32 %0, %0;" : "+f"(x));
    return x;
}

__device__ __forceinline__ void mma_tf32(float (&d)[4],
                                         const float (&a)[4],
                                         const float (&b)[2]) {
    asm volatile(
        "mma.sync.aligned.m16n8k8.row.col.f32.tf32.tf32.f32 "
        "{%0,%1,%2,%3}, {%4,%5,%6,%7}, {%8,%9}, {%0,%1,%2,%3};\n"
        : "+f"(d[0]), "+f"(d[1]), "+f"(d[2]), "+f"(d[3])
        : "r"(__float_as_uint(a[0])), "r"(__float_as_uint(a[1])),
          "r"(__float_as_uint(a[2])), "r"(__float_as_uint(a[3])),
          "r"(__float_as_uint(b[0])), "r"(__float_as_uint(b[1])));
}

__device__ __forceinline__ uint32_t smem_u32(const void* p) {
    uint32_t a;
    asm("{ .reg .u64 t; cvta.to.shared.u64 t, %1; cvt.u32.u64 %0, t; }"
        : "=r"(a) : "l"(p));
    return a;
}

__device__ __forceinline__ void cpa16(uint32_t dst, const float* src, int sz) {
    asm volatile("cp.async.cg.shared.global [%0], [%1], 16, %2;"
                 :: "r"(dst), "l"(src), "r"(sz));
}
__device__ __forceinline__ void cpa_commit() {
    asm volatile("cp.async.commit_group;" ::: "memory");
}
template <int N>
__device__ __forceinline__ void cpa_wait() {
    asm volatile("cp.async.wait_group %0;" :: "n"(N) : "memory");
}

// ---------------------------------------------------------------------------
// Embedding
// ---------------------------------------------------------------------------
__global__ void embed_kernel(const int* __restrict__ tokens,
                             const float* __restrict__ tok,
                             const float* __restrict__ pos,
                             float* __restrict__ x) {
    int n = blockIdx.x;
    int t = n % TSEQ;
    int tk = tokens[n];
    const float* tr = tok + (size_t)tk * CDIM;
    const float* pr = pos + (size_t)t * CDIM;
    float* xr = x + (size_t)n * CDIM;
    for (int c = threadIdx.x; c < CDIM; c += blockDim.x)
        xr[c] = tr[c] + pr[c];
}

// ---------------------------------------------------------------------------
// LayerNorm: warp per row, 8 rows/block, row cached in regs. tf32-rounded out.
// ---------------------------------------------------------------------------
__global__ __launch_bounds__(256)
void ln_kernel(const float* __restrict__ x,
               const float* __restrict__ w,
               const float* __restrict__ b,
               float* __restrict__ out) {
    const int lane = threadIdx.x & 31;
    const int wrp  = threadIdx.x >> 5;
    const int n = blockIdx.x * 8 + wrp;
    const float* xr = x + (size_t)n * CDIM;

    float4 v[6];
    float s = 0.f, s2 = 0.f;
    #pragma unroll
    for (int i = 0; i < 6; i++) {
        v[i] = *(const float4*)(xr + i * 128 + lane * 4);
        s  += v[i].x + v[i].y + v[i].z + v[i].w;
        s2 += v[i].x * v[i].x + v[i].y * v[i].y
            + v[i].z * v[i].z + v[i].w * v[i].w;
    }
    #pragma unroll
    for (int o = 16; o; o >>= 1) {
        s  += __shfl_xor_sync(~0u, s,  o);
        s2 += __shfl_xor_sync(~0u, s2, o);
    }
    float m = s / CDIM;
    float var = s2 / CDIM - m * m;
    float r = rsqrtf(var + 1e-5f);

    float* orow = out + (size_t)n * CDIM;
    #pragma unroll
    for (int i = 0; i < 6; i++) {
        int c = i * 128 + lane * 4;
        float4 wv = *(const float4*)(w + c);
        float4 bv = *(const float4*)(b + c);
        float4 o;
        o.x = f2tf32((v[i].x - m) * r * wv.x + bv.x);
        o.y = f2tf32((v[i].y - m) * r * wv.y + bv.y);
        o.z = f2tf32((v[i].z - m) * r * wv.z + bv.z);
        o.w = f2tf32((v[i].w - m) * r * wv.w + bv.w);
        *(float4*)(orow + c) = o;
    }
}

// ---------------------------------------------------------------------------
// TF32 NT GEMM, cp.async 2-stage pipeline (64KB smem), 2 blocks/SM,
// ONE __syncthreads per K-chunk: wait(it) -> bar -> issue(it+1) -> compute(it).
// Buffer (it+1)&1's last readers (iteration it-1) are fenced by this bar.
// BK=32, optional split-K. rnd=1: tf32-round plain-store outputs (QKV GEMM).
// ---------------------------------------------------------------------------
#define GSTAGE_F 8192
#define GSMEM_BYTES (2 * GSTAGE_F * 4)   // 64 KB

__device__ __forceinline__ int gsw(int r, int k) {
    return r * 32 + (((k >> 2) ^ (r & 7)) << 2) + (k & 3);
}

__global__ __launch_bounds__(256, 2)
void gemm_tf32_kernel(const float* __restrict__ A, const float* __restrict__ W,
                      const float* __restrict__ bias, const float* __restrict__ res,
                      float* __restrict__ C, int N, int M, int K, int gelu,
                      int rnd) {
    extern __shared__ __align__(16) float smf[];

    const int tid  = threadIdx.x;
    const int lane = tid & 31;
    const int wid  = tid >> 5;
    const int g    = lane >> 2;
    const int tig  = lane & 3;
    const int warp_m = wid >> 2;
    const int warp_n = wid & 3;
    const int bm = blockIdx.y * 128;
    const int bn = blockIdx.x * 128;
    const int S     = gridDim.z;
    const int split = blockIdx.z;
    const int Ks     = K / S;
    const int k0base = split * Ks;
    const uint32_t sbase = smem_u32(smf);

    const int lr = tid >> 3;
    const int lc = tid & 7;
    const uint32_t soff = (uint32_t)(lr * 32 + ((lc ^ (lr & 7)) << 2)) * 4u;

    float acc[4][4][4];
    #pragma unroll
    for (int mt = 0; mt < 4; mt++)
        #pragma unroll
        for (int nt = 0; nt < 4; nt++)
            #pragma unroll
            for (int r = 0; r < 4; r++) acc[mt][nt][r] = 0.f;

    const int KT = Ks / 32;

    auto issue = [&](int j) {
        const int k0 = k0base + j * 32;
        const uint32_t ab = sbase + (uint32_t)(j & 1) * GSTAGE_F * 4u;
        const uint32_t bb = ab + 4096u * 4u;
        #pragma unroll
        for (int i = 0; i < 4; i++) {
            int r = lr + i * 32;
            uint32_t rowoff = soff + (uint32_t)i * 32u * 32u * 4u;
            cpa16(ab + rowoff, A + (size_t)(bm + r) * K + k0 + lc * 4, 16);
            int m = bn + r;
            const float* ws = W + (size_t)(m < M ? m : 0) * K + k0 + lc * 4;
            cpa16(bb + rowoff, ws, (m < M) ? 16 : 0);
        }
    };

    issue(0); cpa_commit();

    for (int it = 0; it < KT; it++) {
        cpa_wait<0>();        // drain chunk it (issued last iteration)
        __syncthreads();      // data visible; prior readers of buf (it+1)&1 fenced

        if (it + 1 < KT) { issue(it + 1); cpa_commit(); }

        const float* Asm = smf + (it & 1) * GSTAGE_F;
        const float* Bsm = Asm + 4096;

        #pragma unroll
        for (int ks = 0; ks < 4; ks++) {
            const int kb = ks * 8;
            float a[4][4], b[4][2];
            #pragma unroll
            for (int mt = 0; mt < 4; mt++) {
                int m0 = warp_m * 64 + mt * 16;
                a[mt][0] = Asm[gsw(m0 + g,     kb + tig)];
                a[mt][1] = Asm[gsw(m0 + g + 8, kb + tig)];
                a[mt][2] = Asm[gsw(m0 + g,     kb + tig + 4)];
                a[mt][3] = Asm[gsw(m0 + g + 8, kb + tig + 4)];
            }
            #pragma unroll
            for (int nt = 0; nt < 4; nt++) {
                int n0 = warp_n * 32 + nt * 8;
                b[nt][0] = f2tf32(Bsm[gsw(n0 + g, kb + tig)]);
                b[nt][1] = f2tf32(Bsm[gsw(n0 + g, kb + tig + 4)]);
            }
            #pragma unroll
            for (int mt = 0; mt < 4; mt++)
                #pragma unroll
                for (int nt = 0; nt < 4; nt++)
                    mma_tf32(acc[mt][nt], a[mt], b[nt]);
        }
    }

    #pragma unroll
    for (int mt = 0; mt < 4; mt++) {
        #pragma unroll
        for (int nt = 0; nt < 4; nt++) {
            int col = bn + warp_n * 32 + nt * 8 + 2 * tig;
            #pragma unroll
            for (int rr = 0; rr < 2; rr++) {
                int row = bm + warp_m * 64 + mt * 16 + g + rr * 8;
                float v0 = acc[mt][nt][rr * 2 + 0];
                float v1 = acc[mt][nt][rr * 2 + 1];
                size_t idx = (size_t)row * M + col;
                if (S > 1) {
                    if (split == 0 && bias) { v0 += bias[col]; v1 += bias[col + 1]; }
                    atomicAdd(&C[idx],     v0);
                    atomicAdd(&C[idx + 1], v1);
                    continue;
                }
                if (bias) { v0 += bias[col]; if (col + 1 < M) v1 += bias[col + 1]; }
                if (gelu) {
                    float u = v0;
                    v0 = f2tf32(0.5f * u * (1.f + tanhf(0.7978845608028654f *
                                                 (u + 0.044715f * u * u * u))));
                    u = v1;
                    v1 = f2tf32(0.5f * u * (1.f + tanhf(0.7978845608028654f *
                                                 (u + 0.044715f * u * u * u))));
                } else if (rnd) {
                    v0 = f2tf32(v0);
                    v1 = f2tf32(v1);
                }
                if (col + 1 < M) {
                    if (res) { v0 += res[idx]; v1 += res[idx + 1]; }
                    C[idx]     = v0;
                    C[idx + 1] = v1;
                } else if (col < M) {
                    if (res) v0 += res[idx];
                    C[idx] = v0;
                }
            }
        }
    }
}

// ---------------------------------------------------------------------------
// Tensor-core flash attention (tf32 mma), cp.async double-buffered K/V.
// (unchanged from R13 — validated at 55.8us/launch, rel_err 8.33e-4)
// ---------------------------------------------------------------------------
#define ATQ 64
#define ATK 64
#define LOG2E 1.44269504088896f
#define ATTN_SMEM (5 * 4096 * 4)   // 81920 B

__device__ __forceinline__ int tswz(int r, int c) {
    return r * 64 + ((((c >> 2) ^ ((r + (r >> 4)) & 15))) << 2) + (c & 3);
}
__device__ __forceinline__ int vswz(int r, int c) {
    return r * 64 + ((((c >> 2) ^ ((r & 3) << 1))) << 2) + (c & 3);
}

__global__ __launch_bounds__(128)
void attn_kernel(const float* __restrict__ qkv, float* __restrict__ out) {
    extern __shared__ float sm[];
    float* Qs = sm;                       // [64][64] tswz

    const int qt = gridDim.x - 1 - blockIdx.x;   // heavy tiles first
    const int bh = blockIdx.y;
    const int b  = bh / NHEAD, h = bh % NHEAD;
    const int q0 = qt * ATQ;
    const int tid  = threadIdx.x;
    const int lane = tid & 31;
    const int wid  = tid >> 5;
    const int g    = lane >> 2;
    const int tig  = lane & 3;
    const int m0   = wid * 16;
    const size_t rstride = 3 * CDIM;
    const float qsc = 0.125f * LOG2E;
    const uint32_t sbase = smem_u32(sm);

    // ---- stage Q (scaled + tf32 RNA) ----
    #pragma unroll
    for (int i = 0; i < 8; i++) {
        int f = i * 128 + tid;
        int r = f >> 4, c4 = (f & 15) * 4;
        float4 v = *(const float4*)(qkv + (size_t)(b * TSEQ + q0 + r) * rstride
                                    + h * DHEAD + c4);
        v.x = f2tf32(v.x * qsc); v.y = f2tf32(v.y * qsc);
        v.z = f2tf32(v.z * qsc); v.w = f2tf32(v.w * qsc);
        *(float4*)&Qs[tswz(r, c4)] = v;
    }

    // cp.async K/V tile loader: buffer (jt&1)
    const int lr0 = tid >> 4;      // 0..7
    const int lch = tid & 15;      // 16B chunk in row
    auto issueKV = [&](int jt2) {
        if (jt2 > qt) return;
        const int jr = jt2 * ATK;
        const uint32_t kbase = sbase + (4096u + (uint32_t)(jt2 & 1) * 8192u) * 4u;
        const uint32_t vbase = kbase + 4096u * 4u;
        #pragma unroll
        for (int i = 0; i < 8; i++) {
            int r = lr0 + i * 8;
            const float* src = qkv + (size_t)(b * TSEQ + jr + r) * rstride
                               + h * DHEAD + lch * 4;
            uint32_t koff = (uint32_t)(r * 64 + ((lch ^ ((r + (r >> 4)) & 15)) << 2)) * 4u;
            uint32_t voff = (uint32_t)(r * 64 + ((lch ^ ((r & 3) << 1)) << 2)) * 4u;
            cpa16(kbase + koff, src + CDIM,     16);
            cpa16(vbase + voff, src + 2 * CDIM, 16);
        }
    };

    issueKV(0); cpa_commit();

    float mrow[2] = {-1e30f, -1e30f};
    float lrow[2] = {0.f, 0.f};
    float O[8][4];
    #pragma unroll
    for (int nt = 0; nt < 8; nt++)
        #pragma unroll
        for (int r = 0; r < 4; r++) O[nt][r] = 0.f;

    const int src1 = (g << 2) | (tig >> 1);
    const int src2 = src1 + 2;
    const bool odd = (tig & 1);

    for (int jt = 0; jt <= qt; jt++) {
        issueKV(jt + 1); cpa_commit();
        cpa_wait<1>();
        __syncthreads();

        const float* Ks = sm + 4096 + (jt & 1) * 8192;
        const float* Vs = Ks + 4096;

        // ---- GEMM1: S = Q K^T  (warp tile 16 x 64) ----
        float s[8][4];
        #pragma unroll
        for (int nt = 0; nt < 8; nt++)
            #pragma unroll
            for (int r = 0; r < 4; r++) s[nt][r] = 0.f;

        #pragma unroll
        for (int ks = 0; ks < 8; ks++) {
            const int kb = ks * 8;
            float a[4];
            a[0] = Qs[tswz(m0 + g,     kb + tig)];
            a[1] = Qs[tswz(m0 + g + 8, kb + tig)];
            a[2] = Qs[tswz(m0 + g,     kb + tig + 4)];
            a[3] = Qs[tswz(m0 + g + 8, kb + tig + 4)];
            #pragma unroll
            for (int nt = 0; nt < 8; nt++) {
                float bb[2];
                bb[0] = Ks[tswz(nt * 8 + g, kb + tig)];
                bb[1] = Ks[tswz(nt * 8 + g, kb + tig + 4)];
                mma_tf32(s[nt], a, bb);
            }
        }

        // ---- causal mask: only the diagonal block needs it ----
        if (jt == qt) {
            const int r0 = m0 + g, r1 = r0 + 8;   // local rows (q0 == jb here)
            #pragma unroll
            for (int nt = 0; nt < 8; nt++) {
                int c0 = nt * 8 + 2 * tig;
                if (c0     > r0) s[nt][0] = -1e30f;
                if (c0 + 1 > r0) s[nt][1] = -1e30f;
                if (c0     > r1) s[nt][2] = -1e30f;
                if (c0 + 1 > r1) s[nt][3] = -1e30f;
            }
        }

        // ---- online softmax ----
        float rx0 = -1e30f, rx1 = -1e30f;
        #pragma unroll
        for (int nt = 0; nt < 8; nt++) {
            rx0 = fmaxf(rx0, fmaxf(s[nt][0], s[nt][1]));
            rx1 = fmaxf(rx1, fmaxf(s[nt][2], s[nt][3]));
        }
        rx0 = fmaxf(rx0, __shfl_xor_sync(~0u, rx0, 1));
        rx0 = fmaxf(rx0, __shfl_xor_sync(~0u, rx0, 2));
        rx1 = fmaxf(rx1, __shfl_xor_sync(~0u, rx1, 1));
        rx1 = fmaxf(rx1, __shfl_xor_sync(~0u, rx1, 2));

        float mn0 = fmaxf(mrow[0], rx0);
        float mn1 = fmaxf(mrow[1], rx1);
        float fac0 = exp2f(mrow[0] - mn0);
        float fac1 = exp2f(mrow[1] - mn1);
        float ps0 = 0.f, ps1 = 0.f;
        #pragma unroll
        for (int nt = 0; nt < 8; nt++) {
            float p0 = f2tf32(exp2f(s[nt][0] - mn0));
            float p1 = f2tf32(exp2f(s[nt][1] - mn0));
            float p2 = f2tf32(exp2f(s[nt][2] - mn1));
            float p3 = f2tf32(exp2f(s[nt][3] - mn1));
            s[nt][0] = p0; s[nt][1] = p1; s[nt][2] = p2; s[nt][3] = p3;
            ps0 += p0 + p1; ps1 += p2 + p3;
        }
        ps0 += __shfl_xor_sync(~0u, ps0, 1);
        ps0 += __shfl_xor_sync(~0u, ps0, 2);
        ps1 += __shfl_xor_sync(~0u, ps1, 1);
        ps1 += __shfl_xor_sync(~0u, ps1, 2);
        lrow[0] = lrow[0] * fac0 + ps0;
        lrow[1] = lrow[1] * fac1 + ps1;
        mrow[0] = mn0; mrow[1] = mn1;

        #pragma unroll
        for (int nt = 0; nt < 8; nt++) {
            O[nt][0] *= fac0; O[nt][1] *= fac0;
            O[nt][2] *= fac1; O[nt][3] *= fac1;
        }

        // ---- GEMM2: O += P V  (A-frags via quad shuffles; B from vswz V) ----
        #pragma unroll
        for (int ks = 0; ks < 8; ks++) {
            float v0 = __shfl_sync(~0u, s[ks][0], src1);
            float v1 = __shfl_sync(~0u, s[ks][1], src1);
            float v2 = __shfl_sync(~0u, s[ks][2], src1);
            float v3 = __shfl_sync(~0u, s[ks][3], src1);
            float w0 = __shfl_sync(~0u, s[ks][0], src2);
            float w1 = __shfl_sync(~0u, s[ks][1], src2);
            float w2 = __shfl_sync(~0u, s[ks][2], src2);
            float w3 = __shfl_sync(~0u, s[ks][3], src2);
            float a[4];
            a[0] = odd ? v1 : v0;
            a[1] = odd ? v3 : v2;
            a[2] = odd ? w1 : w0;
            a[3] = odd ? w3 : w2;
            const int kb = ks * 8;
            #pragma unroll
            for (int nt = 0; nt < 8; nt++) {
                float bb[2];
                bb[0] = Vs[vswz(kb + tig,     nt * 8 + g)];
                bb[1] = Vs[vswz(kb + tig + 4, nt * 8 + g)];
                mma_tf32(O[nt], a, bb);
            }
        }
        __syncthreads();   // compute done before buffer (jt&1) is overwritten
    }

    float inv0 = 1.f / lrow[0];
    float inv1 = 1.f / lrow[1];
    float* o0 = out + (size_t)(b * TSEQ + q0 + m0 + g) * CDIM + h * DHEAD;
    float* o1 = o0 + 8 * CDIM;
    #pragma unroll
    for (int nt = 0; nt < 8; nt++) {
        int c = nt * 8 + 2 * tig;
        float2 u0 = make_float2(f2tf32(O[nt][0] * inv0), f2tf32(O[nt][1] * inv0));
        float2 u1 = make_float2(f2tf32(O[nt][2] * inv1), f2tf32(O[nt][3] * inv1));
        *(float2*)(o0 + c) = u0;
        *(float2*)(o1 + c) = u1;
    }
}

// ---------------------------------------------------------------------------
// Launcher
// ---------------------------------------------------------------------------
extern "C" void kernel_launch(void* const* d_in, const int* in_sizes, int n_in,
                              void* d_out, int out_size) {
    const int*   tokens    = (const int*)  d_in[0];
    const float* tok_embed = (const float*)d_in[1];
    const float* pos_embed = (const float*)d_in[2];
    const float* ln1_w     = (const float*)d_in[3];
    const float* ln1_b     = (const float*)d_in[4];
    const float* qkv_w     = (const float*)d_in[5];
    const float* qkv_b     = (const float*)d_in[6];
    const float* proj_w    = (const float*)d_in[7];
    const float* proj_b    = (const float*)d_in[8];
    const float* ln2_w     = (const float*)d_in[9];
    const float* ln2_b     = (const float*)d_in[10];
    const float* fc_w      = (const float*)d_in[11];
    const float* fc_b      = (const float*)d_in[12];
    const float* fc2_w     = (const float*)d_in[13];
    const float* fc2_b     = (const float*)d_in[14];
    const float* lnf_w     = (const float*)d_in[15];
    const float* lnf_b     = (const float*)d_in[16];
    float* logits = (float*)d_out;

    float *x, *h, *qkv, *att, *ffn;
    cudaGetSymbolAddress((void**)&x,   g_x);
    cudaGetSymbolAddress((void**)&h,   g_h);
    cudaGetSymbolAddress((void**)&qkv, g_qkv);
    cudaGetSymbolAddress((void**)&att, g_att);
    cudaGetSymbolAddress((void**)&ffn, g_ffn);

    cudaFuncSetAttribute(attn_kernel,
                         cudaFuncAttributeMaxDynamicSharedMemorySize, ATTN_SMEM);
    cudaFuncSetAttribute(gemm_tf32_kernel,
                         cudaFuncAttributeMaxDynamicSharedMemorySize, GSMEM_BYTES);

    embed_kernel<<<NROW, 256>>>(tokens, tok_embed, pos_embed, x);

    const int NB = NROW / 128;   // 16 row-blocks
    for (int l = 0; l < NLAYER; l++) {
        const float* l1w = ln1_w  + (size_t)l * CDIM;
        const float* l1b = ln1_b  + (size_t)l * CDIM;
        const float* qw  = qkv_w  + (size_t)l * 3 * CDIM * CDIM;
        const float* qb  = qkv_b  + (size_t)l * 3 * CDIM;
        const float* pw  = proj_w + (size_t)l * CDIM * CDIM;
        const float* pb  = proj_b + (size_t)l * CDIM;
        const float* l2w = ln2_w  + (size_t)l * CDIM;
        const float* l2b = ln2_b  + (size_t)l * CDIM;
        const float* fw  = fc_w   + (size_t)l * FFDIM * CDIM;
        const float* fb  = fc_b   + (size_t)l * FFDIM;
        const float* f2w = fc2_w  + (size_t)l * CDIM * FFDIM;
        const float* f2b = fc2_b  + (size_t)l * CDIM;

        ln_kernel<<<NROW / 8, 256>>>(x, l1w, l1b, h);
        // qkv: rnd=1 so attention's K/V are exact tf32 values
        gemm_tf32_kernel<<<dim3(3 * CDIM / 128, NB), 256, GSMEM_BYTES>>>(
            h, qw, qb, nullptr, qkv, NROW, 3 * CDIM, CDIM, 0, 1);
        attn_kernel<<<dim3(TSEQ / ATQ, BSZ * NHEAD), 128, ATTN_SMEM>>>(qkv, att);
        // proj: split-K=3, x += att @ pw^T + pb (atomic, in place)
        gemm_tf32_kernel<<<dim3(CDIM / 128, NB, 3), 256, GSMEM_BYTES>>>(
            att, pw, pb, nullptr, x, NROW, CDIM, CDIM, 0, 0);
        ln_kernel<<<NROW / 8, 256>>>(x, l2w, l2b, h);
        gemm_tf32_kernel<<<dim3(FFDIM / 128, NB), 256, GSMEM_BYTES>>>(
            h, fw, fb, nullptr, ffn, NROW, FFDIM, CDIM, 1, 0);
        // fc2: split-K=3, x += ffn @ f2w^T + f2b (atomic, in place)
        gemm_tf32_kernel<<<dim3(CDIM / 128, NB, 3), 256, GSMEM_BYTES>>>(
            ffn, f2w, f2b, nullptr, x, NROW, CDIM, FFDIM, 0, 0);
    }

    ln_kernel<<<NROW / 8, 256>>>(x, lnf_w, lnf_b, h);
    gemm_tf32_kernel<<<dim3((VOCAB + 127) / 128, NB), 256, GSMEM_BYTES>>>(
        h, tok_embed, nullptr, nullptr, logits, NROW, VOCAB, CDIM, 0, 0);
}

// round 16
// speedup vs baseline: 1.3895x; 1.1156x over previous
#include <cuda_runtime.h>
#include <math.h>
#include <stdint.h>

// GPT-2 small config
#define BSZ   2
#define TSEQ  1024
#define CDIM  768
#define FFDIM 3072
#define NHEAD 12
#define NLAYER 12
#define DHEAD 64
#define VOCAB 50257
#define NROW  (BSZ * TSEQ)   // 2048

// ---------------------------------------------------------------------------
// Scratch (device globals — no allocation allowed)
// ---------------------------------------------------------------------------
__device__ float g_x  [NROW * CDIM];
__device__ float g_h  [NROW * CDIM];
__device__ float g_qkv[NROW * 3 * CDIM];
__device__ float g_att[NROW * CDIM];
__device__ float g_ffn[NROW * FFDIM];

// ---------------------------------------------------------------------------
// Helpers
// ---------------------------------------------------------------------------
__device__ __forceinline__ float f2tf32(float x) {
    asm("cvt.rna.tf32.f32 %0, %0;" : "+f"(x));
    return x;
}

__device__ __forceinline__ void mma_tf32(float (&d)[4],
                                         const float (&a)[4],
                                         const float (&b)[2]) {
    asm volatile(
        "mma.sync.aligned.m16n8k8.row.col.f32.tf32.tf32.f32 "
        "{%0,%1,%2,%3}, {%4,%5,%6,%7}, {%8,%9}, {%0,%1,%2,%3};\n"
        : "+f"(d[0]), "+f"(d[1]), "+f"(d[2]), "+f"(d[3])
        : "r"(__float_as_uint(a[0])), "r"(__float_as_uint(a[1])),
          "r"(__float_as_uint(a[2])), "r"(__float_as_uint(a[3])),
          "r"(__float_as_uint(b[0])), "r"(__float_as_uint(b[1])));
}

__device__ __forceinline__ uint32_t smem_u32(const void* p) {
    uint32_t a;
    asm("{ .reg .u64 t; cvta.to.shared.u64 t, %1; cvt.u32.u64 %0, t; }"
        : "=r"(a) : "l"(p));
    return a;
}

__device__ __forceinline__ void cpa16(uint32_t dst, const float* src, int sz) {
    asm volatile("cp.async.cg.shared.global [%0], [%1], 16, %2;"
                 :: "r"(dst), "l"(src), "r"(sz));
}
__device__ __forceinline__ void cpa_commit() {
    asm volatile("cp.async.commit_group;" ::: "memory");
}
template <int N>
__device__ __forceinline__ void cpa_wait() {
    asm volatile("cp.async.wait_group %0;" :: "n"(N) : "memory");
}

// ---------------------------------------------------------------------------
// Embedding
// ---------------------------------------------------------------------------
__global__ void embed_kernel(const int* __restrict__ tokens,
                             const float* __restrict__ tok,
                             const float* __restrict__ pos,
                             float* __restrict__ x) {
    int n = blockIdx.x;
    int t = n % TSEQ;
    int tk = tokens[n];
    const float* tr = tok + (size_t)tk * CDIM;
    const float* pr = pos + (size_t)t * CDIM;
    float* xr = x + (size_t)n * CDIM;
    for (int c = threadIdx.x; c < CDIM; c += blockDim.x)
        xr[c] = tr[c] + pr[c];
}

// ---------------------------------------------------------------------------
// LayerNorm: warp per row, 8 rows/block, row cached in regs. tf32-rounded out.
// ---------------------------------------------------------------------------
__global__ __launch_bounds__(256)
void ln_kernel(const float* __restrict__ x,
               const float* __restrict__ w,
               const float* __restrict__ b,
               float* __restrict__ out) {
    const int lane = threadIdx.x & 31;
    const int wrp  = threadIdx.x >> 5;
    const int n = blockIdx.x * 8 + wrp;
    const float* xr = x + (size_t)n * CDIM;

    float4 v[6];
    float s = 0.f, s2 = 0.f;
    #pragma unroll
    for (int i = 0; i < 6; i++) {
        v[i] = *(const float4*)(xr + i * 128 + lane * 4);
        s  += v[i].x + v[i].y + v[i].z + v[i].w;
        s2 += v[i].x * v[i].x + v[i].y * v[i].y
            + v[i].z * v[i].z + v[i].w * v[i].w;
    }
    #pragma unroll
    for (int o = 16; o; o >>= 1) {
        s  += __shfl_xor_sync(~0u, s,  o);
        s2 += __shfl_xor_sync(~0u, s2, o);
    }
    float m = s / CDIM;
    float var = s2 / CDIM - m * m;
    float r = rsqrtf(var + 1e-5f);

    float* orow = out + (size_t)n * CDIM;
    #pragma unroll
    for (int i = 0; i < 6; i++) {
        int c = i * 128 + lane * 4;
        float4 wv = *(const float4*)(w + c);
        float4 bv = *(const float4*)(b + c);
        float4 o;
        o.x = f2tf32((v[i].x - m) * r * wv.x + bv.x);
        o.y = f2tf32((v[i].y - m) * r * wv.y + bv.y);
        o.z = f2tf32((v[i].z - m) * r * wv.z + bv.z);
        o.w = f2tf32((v[i].w - m) * r * wv.w + bv.w);
        *(float4*)(orow + c) = o;
    }
}

// ---------------------------------------------------------------------------
// TF32 NT GEMM, cp.async 3-stage pipeline (96KB smem), 2 blocks/SM
// (192KB of 228KB per-SM carveout). One __syncthreads per chunk:
// wait<1>(chunk it done) -> bar -> issue(it+2) -> compute(it).
// Buffer (it+2)%3's last readers were compute(it-1), fenced by this bar.
// BK=32, optional split-K. rnd=1: tf32-round plain-store outputs (QKV GEMM).
// ---------------------------------------------------------------------------
#define GSTAGE_F 8192
#define GSMEM_BYTES (3 * GSTAGE_F * 4)   // 96 KB

__device__ __forceinline__ int gsw(int r, int k) {
    return r * 32 + (((k >> 2) ^ (r & 7)) << 2) + (k & 3);
}

__global__ __launch_bounds__(256, 2)
void gemm_tf32_kernel(const float* __restrict__ A, const float* __restrict__ W,
                      const float* __restrict__ bias, const float* __restrict__ res,
                      float* __restrict__ C, int N, int M, int K, int gelu,
                      int rnd) {
    extern __shared__ __align__(16) float smf[];

    const int tid  = threadIdx.x;
    const int lane = tid & 31;
    const int wid  = tid >> 5;
    const int g    = lane >> 2;
    const int tig  = lane & 3;
    const int warp_m = wid >> 2;
    const int warp_n = wid & 3;
    const int bm = blockIdx.y * 128;
    const int bn = blockIdx.x * 128;
    const int S     = gridDim.z;
    const int split = blockIdx.z;
    const int Ks     = K / S;
    const int k0base = split * Ks;
    const uint32_t sbase = smem_u32(smf);

    const int lr = tid >> 3;
    const int lc = tid & 7;
    const uint32_t soff = (uint32_t)(lr * 32 + ((lc ^ (lr & 7)) << 2)) * 4u;

    float acc[4][4][4];
    #pragma unroll
    for (int mt = 0; mt < 4; mt++)
        #pragma unroll
        for (int nt = 0; nt < 4; nt++)
            #pragma unroll
            for (int r = 0; r < 4; r++) acc[mt][nt][r] = 0.f;

    const int KT = Ks / 32;

    auto issue = [&](int j) {
        const int k0 = k0base + j * 32;
        const uint32_t ab = sbase + (uint32_t)(j % 3) * GSTAGE_F * 4u;
        const uint32_t bb = ab + 4096u * 4u;
        #pragma unroll
        for (int i = 0; i < 4; i++) {
            int r = lr + i * 32;
            uint32_t rowoff = soff + (uint32_t)i * 32u * 32u * 4u;
            cpa16(ab + rowoff, A + (size_t)(bm + r) * K + k0 + lc * 4, 16);
            int m = bn + r;
            const float* ws = W + (size_t)(m < M ? m : 0) * K + k0 + lc * 4;
            cpa16(bb + rowoff, ws, (m < M) ? 16 : 0);
        }
    };

    issue(0); cpa_commit();
    if (KT > 1) { issue(1); cpa_commit(); }

    for (int it = 0; it < KT; it++) {
        cpa_wait<1>();        // chunk it complete (it+1 may still be in flight)
        __syncthreads();      // data visible; compute(it-1) readers fenced

        if (it + 2 < KT) { issue(it + 2); cpa_commit(); }

        const float* Asm = smf + (it % 3) * GSTAGE_F;
        const float* Bsm = Asm + 4096;

        #pragma unroll
        for (int ks = 0; ks < 4; ks++) {
            const int kb = ks * 8;
            float a[4][4], b[4][2];
            #pragma unroll
            for (int mt = 0; mt < 4; mt++) {
                int m0 = warp_m * 64 + mt * 16;
                a[mt][0] = Asm[gsw(m0 + g,     kb + tig)];
                a[mt][1] = Asm[gsw(m0 + g + 8, kb + tig)];
                a[mt][2] = Asm[gsw(m0 + g,     kb + tig + 4)];
                a[mt][3] = Asm[gsw(m0 + g + 8, kb + tig + 4)];
            }
            #pragma unroll
            for (int nt = 0; nt < 4; nt++) {
                int n0 = warp_n * 32 + nt * 8;
                b[nt][0] = f2tf32(Bsm[gsw(n0 + g, kb + tig)]);
                b[nt][1] = f2tf32(Bsm[gsw(n0 + g, kb + tig + 4)]);
            }
            #pragma unroll
            for (int mt = 0; mt < 4; mt++)
                #pragma unroll
                for (int nt = 0; nt < 4; nt++)
                    mma_tf32(acc[mt][nt], a[mt], b[nt]);
        }
    }

    #pragma unroll
    for (int mt = 0; mt < 4; mt++) {
        #pragma unroll
        for (int nt = 0; nt < 4; nt++) {
            int col = bn + warp_n * 32 + nt * 8 + 2 * tig;
            #pragma unroll
            for (int rr = 0; rr < 2; rr++) {
                int row = bm + warp_m * 64 + mt * 16 + g + rr * 8;
                float v0 = acc[mt][nt][rr * 2 + 0];
                float v1 = acc[mt][nt][rr * 2 + 1];
                size_t idx = (size_t)row * M + col;
                if (S > 1) {
                    if (split == 0 && bias) { v0 += bias[col]; v1 += bias[col + 1]; }
                    atomicAdd(&C[idx],     v0);
                    atomicAdd(&C[idx + 1], v1);
                    continue;
                }
                if (bias) { v0 += bias[col]; if (col + 1 < M) v1 += bias[col + 1]; }
                if (gelu) {
                    float u = v0;
                    v0 = f2tf32(0.5f * u * (1.f + tanhf(0.7978845608028654f *
                                                 (u + 0.044715f * u * u * u))));
                    u = v1;
                    v1 = f2tf32(0.5f * u * (1.f + tanhf(0.7978845608028654f *
                                                 (u + 0.044715f * u * u * u))));
                } else if (rnd) {
                    v0 = f2tf32(v0);
                    v1 = f2tf32(v1);
                }
                if (col + 1 < M) {
                    if (res) { v0 += res[idx]; v1 += res[idx + 1]; }
                    C[idx]     = v0;
                    C[idx + 1] = v1;
                } else if (col < M) {
                    if (res) v0 += res[idx];
                    C[idx] = v0;
                }
            }
        }
    }
}

// ---------------------------------------------------------------------------
// Tensor-core flash attention (tf32 mma), cp.async double-buffered K/V.
// (unchanged from R14 — validated at 52.9us/launch, rel_err 8.34e-4)
// ---------------------------------------------------------------------------
#define ATQ 64
#define ATK 64
#define LOG2E 1.44269504088896f
#define ATTN_SMEM (5 * 4096 * 4)   // 81920 B

__device__ __forceinline__ int tswz(int r, int c) {
    return r * 64 + ((((c >> 2) ^ ((r + (r >> 4)) & 15))) << 2) + (c & 3);
}
__device__ __forceinline__ int vswz(int r, int c) {
    return r * 64 + ((((c >> 2) ^ ((r & 3) << 1))) << 2) + (c & 3);
}

__global__ __launch_bounds__(128)
void attn_kernel(const float* __restrict__ qkv, float* __restrict__ out) {
    extern __shared__ float sm[];
    float* Qs = sm;                       // [64][64] tswz

    const int qt = gridDim.x - 1 - blockIdx.x;   // heavy tiles first
    const int bh = blockIdx.y;
    const int b  = bh / NHEAD, h = bh % NHEAD;
    const int q0 = qt * ATQ;
    const int tid  = threadIdx.x;
    const int lane = tid & 31;
    const int wid  = tid >> 5;
    const int g    = lane >> 2;
    const int tig  = lane & 3;
    const int m0   = wid * 16;
    const size_t rstride = 3 * CDIM;
    const float qsc = 0.125f * LOG2E;
    const uint32_t sbase = smem_u32(sm);

    // ---- stage Q (scaled + tf32 RNA) ----
    #pragma unroll
    for (int i = 0; i < 8; i++) {
        int f = i * 128 + tid;
        int r = f >> 4, c4 = (f & 15) * 4;
        float4 v = *(const float4*)(qkv + (size_t)(b * TSEQ + q0 + r) * rstride
                                    + h * DHEAD + c4);
        v.x = f2tf32(v.x * qsc); v.y = f2tf32(v.y * qsc);
        v.z = f2tf32(v.z * qsc); v.w = f2tf32(v.w * qsc);
        *(float4*)&Qs[tswz(r, c4)] = v;
    }

    // cp.async K/V tile loader: buffer (jt&1)
    const int lr0 = tid >> 4;      // 0..7
    const int lch = tid & 15;      // 16B chunk in row
    auto issueKV = [&](int jt2) {
        if (jt2 > qt) return;
        const int jr = jt2 * ATK;
        const uint32_t kbase = sbase + (4096u + (uint32_t)(jt2 & 1) * 8192u) * 4u;
        const uint32_t vbase = kbase + 4096u * 4u;
        #pragma unroll
        for (int i = 0; i < 8; i++) {
            int r = lr0 + i * 8;
            const float* src = qkv + (size_t)(b * TSEQ + jr + r) * rstride
                               + h * DHEAD + lch * 4;
            uint32_t koff = (uint32_t)(r * 64 + ((lch ^ ((r + (r >> 4)) & 15)) << 2)) * 4u;
            uint32_t voff = (uint32_t)(r * 64 + ((lch ^ ((r & 3) << 1)) << 2)) * 4u;
            cpa16(kbase + koff, src + CDIM,     16);
            cpa16(vbase + voff, src + 2 * CDIM, 16);
        }
    };

    issueKV(0); cpa_commit();

    float mrow[2] = {-1e30f, -1e30f};
    float lrow[2] = {0.f, 0.f};
    float O[8][4];
    #pragma unroll
    for (int nt = 0; nt < 8; nt++)
        #pragma unroll
        for (int r = 0; r < 4; r++) O[nt][r] = 0.f;

    const int src1 = (g << 2) | (tig >> 1);
    const int src2 = src1 + 2;
    const bool odd = (tig & 1);

    for (int jt = 0; jt <= qt; jt++) {
        issueKV(jt + 1); cpa_commit();
        cpa_wait<1>();
        __syncthreads();

        const float* Ks = sm + 4096 + (jt & 1) * 8192;
        const float* Vs = Ks + 4096;

        // ---- GEMM1: S = Q K^T  (warp tile 16 x 64) ----
        float s[8][4];
        #pragma unroll
        for (int nt = 0; nt < 8; nt++)
            #pragma unroll
            for (int r = 0; r < 4; r++) s[nt][r] = 0.f;

        #pragma unroll
        for (int ks = 0; ks < 8; ks++) {
            const int kb = ks * 8;
            float a[4];
            a[0] = Qs[tswz(m0 + g,     kb + tig)];
            a[1] = Qs[tswz(m0 + g + 8, kb + tig)];
            a[2] = Qs[tswz(m0 + g,     kb + tig + 4)];
            a[3] = Qs[tswz(m0 + g + 8, kb + tig + 4)];
            #pragma unroll
            for (int nt = 0; nt < 8; nt++) {
                float bb[2];
                bb[0] = Ks[tswz(nt * 8 + g, kb + tig)];
                bb[1] = Ks[tswz(nt * 8 + g, kb + tig + 4)];
                mma_tf32(s[nt], a, bb);
            }
        }

        // ---- causal mask: only the diagonal block needs it ----
        if (jt == qt) {
            const int r0 = m0 + g, r1 = r0 + 8;   // local rows (q0 == jb here)
            #pragma unroll
            for (int nt = 0; nt < 8; nt++) {
                int c0 = nt * 8 + 2 * tig;
                if (c0     > r0) s[nt][0] = -1e30f;
                if (c0 + 1 > r0) s[nt][1] = -1e30f;
                if (c0     > r1) s[nt][2] = -1e30f;
                if (c0 + 1 > r1) s[nt][3] = -1e30f;
            }
        }

        // ---- online softmax ----
        float rx0 = -1e30f, rx1 = -1e30f;
        #pragma unroll
        for (int nt = 0; nt < 8; nt++) {
            rx0 = fmaxf(rx0, fmaxf(s[nt][0], s[nt][1]));
            rx1 = fmaxf(rx1, fmaxf(s[nt][2], s[nt][3]));
        }
        rx0 = fmaxf(rx0, __shfl_xor_sync(~0u, rx0, 1));
        rx0 = fmaxf(rx0, __shfl_xor_sync(~0u, rx0, 2));
        rx1 = fmaxf(rx1, __shfl_xor_sync(~0u, rx1, 1));
        rx1 = fmaxf(rx1, __shfl_xor_sync(~0u, rx1, 2));

        float mn0 = fmaxf(mrow[0], rx0);
        float mn1 = fmaxf(mrow[1], rx1);
        float fac0 = exp2f(mrow[0] - mn0);
        float fac1 = exp2f(mrow[1] - mn1);
        float ps0 = 0.f, ps1 = 0.f;
        #pragma unroll
        for (int nt = 0; nt < 8; nt++) {
            float p0 = f2tf32(exp2f(s[nt][0] - mn0));
            float p1 = f2tf32(exp2f(s[nt][1] - mn0));
            float p2 = f2tf32(exp2f(s[nt][2] - mn1));
            float p3 = f2tf32(exp2f(s[nt][3] - mn1));
            s[nt][0] = p0; s[nt][1] = p1; s[nt][2] = p2; s[nt][3] = p3;
            ps0 += p0 + p1; ps1 += p2 + p3;
        }
        ps0 += __shfl_xor_sync(~0u, ps0, 1);
        ps0 += __shfl_xor_sync(~0u, ps0, 2);
        ps1 += __shfl_xor_sync(~0u, ps1, 1);
        ps1 += __shfl_xor_sync(~0u, ps1, 2);
        lrow[0] = lrow[0] * fac0 + ps0;
        lrow[1] = lrow[1] * fac1 + ps1;
        mrow[0] = mn0; mrow[1] = mn1;

        #pragma unroll
        for (int nt = 0; nt < 8; nt++) {
            O[nt][0] *= fac0; O[nt][1] *= fac0;
            O[nt][2] *= fac1; O[nt][3] *= fac1;
        }

        // ---- GEMM2: O += P V  (A-frags via quad shuffles; B from vswz V) ----
        #pragma unroll
        for (int ks = 0; ks < 8; ks++) {
            float v0 = __shfl_sync(~0u, s[ks][0], src1);
            float v1 = __shfl_sync(~0u, s[ks][1], src1);
            float v2 = __shfl_sync(~0u, s[ks][2], src1);
            float v3 = __shfl_sync(~0u, s[ks][3], src1);
            float w0 = __shfl_sync(~0u, s[ks][0], src2);
            float w1 = __shfl_sync(~0u, s[ks][1], src2);
            float w2 = __shfl_sync(~0u, s[ks][2], src2);
            float w3 = __shfl_sync(~0u, s[ks][3], src2);
            float a[4];
            a[0] = odd ? v1 : v0;
            a[1] = odd ? v3 : v2;
            a[2] = odd ? w1 : w0;
            a[3] = odd ? w3 : w2;
            const int kb = ks * 8;
            #pragma unroll
            for (int nt = 0; nt < 8; nt++) {
                float bb[2];
                bb[0] = Vs[vswz(kb + tig,     nt * 8 + g)];
                bb[1] = Vs[vswz(kb + tig + 4, nt * 8 + g)];
                mma_tf32(O[nt], a, bb);
            }
        }
        __syncthreads();   // compute done before buffer (jt&1) is overwritten
    }

    float inv0 = 1.f / lrow[0];
    float inv1 = 1.f / lrow[1];
    float* o0 = out + (size_t)(b * TSEQ + q0 + m0 + g) * CDIM + h * DHEAD;
    float* o1 = o0 + 8 * CDIM;
    #pragma unroll
    for (int nt = 0; nt < 8; nt++) {
        int c = nt * 8 + 2 * tig;
        float2 u0 = make_float2(f2tf32(O[nt][0] * inv0), f2tf32(O[nt][1] * inv0));
        float2 u1 = make_float2(f2tf32(O[nt][2] * inv1), f2tf32(O[nt][3] * inv1));
        *(float2*)(o0 + c) = u0;
        *(float2*)(o1 + c) = u1;
    }
}

// ---------------------------------------------------------------------------
// Launcher
// ---------------------------------------------------------------------------
extern "C" void kernel_launch(void* const* d_in, const int* in_sizes, int n_in,
                              void* d_out, int out_size) {
    const int*   tokens    = (const int*)  d_in[0];
    const float* tok_embed = (const float*)d_in[1];
    const float* pos_embed = (const float*)d_in[2];
    const float* ln1_w     = (const float*)d_in[3];
    const float* ln1_b     = (const float*)d_in[4];
    const float* qkv_w     = (const float*)d_in[5];
    const float* qkv_b     = (const float*)d_in[6];
    const float* proj_w    = (const float*)d_in[7];
    const float* proj_b    = (const float*)d_in[8];
    const float* ln2_w     = (const float*)d_in[9];
    const float* ln2_b     = (const float*)d_in[10];
    const float* fc_w      = (const float*)d_in[11];
    const float* fc_b      = (const float*)d_in[12];
    const float* fc2_w     = (const float*)d_in[13];
    const float* fc2_b     = (const float*)d_in[14];
    const float* lnf_w     = (const float*)d_in[15];
    const float* lnf_b     = (const float*)d_in[16];
    float* logits = (float*)d_out;

    float *x, *h, *qkv, *att, *ffn;
    cudaGetSymbolAddress((void**)&x,   g_x);
    cudaGetSymbolAddress((void**)&h,   g_h);
    cudaGetSymbolAddress((void**)&qkv, g_qkv);
    cudaGetSymbolAddress((void**)&att, g_att);
    cudaGetSymbolAddress((void**)&ffn, g_ffn);

    cudaFuncSetAttribute(attn_kernel,
                         cudaFuncAttributeMaxDynamicSharedMemorySize, ATTN_SMEM);
    cudaFuncSetAttribute(gemm_tf32_kernel,
                         cudaFuncAttributeMaxDynamicSharedMemorySize, GSMEM_BYTES);

    embed_kernel<<<NROW, 256>>>(tokens, tok_embed, pos_embed, x);

    const int NB = NROW / 128;   // 16 row-blocks
    for (int l = 0; l < NLAYER; l++) {
        const float* l1w = ln1_w  + (size_t)l * CDIM;
        const float* l1b = ln1_b  + (size_t)l * CDIM;
        const float* qw  = qkv_w  + (size_t)l * 3 * CDIM * CDIM;
        const float* qb  = qkv_b  + (size_t)l * 3 * CDIM;
        const float* pw  = proj_w + (size_t)l * CDIM * CDIM;
        const float* pb  = proj_b + (size_t)l * CDIM;
        const float* l2w = ln2_w  + (size_t)l * CDIM;
        const float* l2b = ln2_b  + (size_t)l * CDIM;
        const float* fw  = fc_w   + (size_t)l * FFDIM * CDIM;
        const float* fb  = fc_b   + (size_t)l * FFDIM;
        const float* f2w = fc2_w  + (size_t)l * CDIM * FFDIM;
        const float* f2b = fc2_b  + (size_t)l * CDIM;

        ln_kernel<<<NROW / 8, 256>>>(x, l1w, l1b, h);
        // qkv: rnd=1 so attention's K/V are exact tf32 values
        gemm_tf32_kernel<<<dim3(3 * CDIM / 128, NB), 256, GSMEM_BYTES>>>(
            h, qw, qb, nullptr, qkv, NROW, 3 * CDIM, CDIM, 0, 1);
        attn_kernel<<<dim3(TSEQ / ATQ, BSZ * NHEAD), 128, ATTN_SMEM>>>(qkv, att);
        // proj: split-K=3, x += att @ pw^T + pb (atomic, in place)
        gemm_tf32_kernel<<<dim3(CDIM / 128, NB, 3), 256, GSMEM_BYTES>>>(
            att, pw, pb, nullptr, x, NROW, CDIM, CDIM, 0, 0);
        ln_kernel<<<NROW / 8, 256>>>(x, l2w, l2b, h);
        gemm_tf32_kernel<<<dim3(FFDIM / 128, NB), 256, GSMEM_BYTES>>>(
            h, fw, fb, nullptr, ffn, NROW, FFDIM, CDIM, 1, 0);
        // fc2: split-K=3, x += ffn @ f2w^T + f2b (atomic, in place)
        gemm_tf32_kernel<<<dim3(CDIM / 128, NB, 3), 256, GSMEM_BYTES>>>(
            ffn, f2w, f2b, nullptr, x, NROW, CDIM, FFDIM, 0, 0);
    }

    ln_kernel<<<NROW / 8, 256>>>(x, lnf_w, lnf_b, h);
    gemm_tf32_kernel<<<dim3((VOCAB + 127) / 128, NB), 256, GSMEM_BYTES>>>(
        h, tok_embed, nullptr, nullptr, logits, NROW, VOCAB, CDIM, 0, 0);
}